// round 7
// baseline (speedup 1.0000x reference)
#include <cuda_runtime.h>
#include <cuda_bf16.h>
#include <cstdint>
#include <math.h>

// Problem constants
#define T_  2048
#define B_  2
#define S_  2048
#define E_  1024
#define H_  16
#define HD_ 64
#define R_  16
#define M_  (T_ * B_)          // 4096 rows for projections
#define BH_ (B_ * H_)          // 32 attention "batches"
#define SCALING 1.0f           // ALPHA / R = 16/16
#define OUT1_ELEMS ((size_t)T_ * B_ * E_)            // 4,194,304
#define OUT2_ELEMS ((size_t)B_ * T_ * S_)            // 8,388,608

// ---------------------------------------------------------------------------
// Static device scratch (no allocations allowed)
// ---------------------------------------------------------------------------
__device__ float g_O[M_ * E_];                        // attention out (fp32)
__device__ float g_P[(size_t)BH_ * T_ * S_];          // 512 MB scores/probs
__device__ float g_Xa[4 * M_ * R_];                   // LoRA-A activations
__device__ __nv_bfloat16 g_Qh[M_ * E_];
__device__ __nv_bfloat16 g_Ql[M_ * E_];
__device__ __nv_bfloat16 g_Kh[M_ * E_];
__device__ __nv_bfloat16 g_Kl[M_ * E_];
__device__ __nv_bfloat16 g_Vh[M_ * E_];
__device__ __nv_bfloat16 g_Vl[M_ * E_];

// ---------------------------------------------------------------------------
// mma.sync helpers (portable path; tcgen05 rejected by plain sm_103 target)
// ---------------------------------------------------------------------------
__device__ __forceinline__ uint32_t smem_u32(const void* p) {
    uint32_t a;
    asm("{ .reg .u64 t; cvta.to.shared.u64 t, %1; cvt.u32.u64 %0, t; }" : "=r"(a) : "l"(p));
    return a;
}
#define LDMATRIX_X4(r, addr) \
    asm volatile("ldmatrix.sync.aligned.m8n8.x4.shared.b16 {%0,%1,%2,%3}, [%4];" \
        : "=r"((r)[0]), "=r"((r)[1]), "=r"((r)[2]), "=r"((r)[3]) : "r"(addr))
#define LDMATRIX_X4_T(r, addr) \
    asm volatile("ldmatrix.sync.aligned.m8n8.x4.trans.shared.b16 {%0,%1,%2,%3}, [%4];" \
        : "=r"((r)[0]), "=r"((r)[1]), "=r"((r)[2]), "=r"((r)[3]) : "r"(addr))
#define MMA_BF16(d, a, b) \
    asm volatile("mma.sync.aligned.m16n8k16.row.col.f32.bf16.bf16.f32 " \
        "{%0,%1,%2,%3}, {%4,%5,%6,%7}, {%8,%9}, {%0,%1,%2,%3};" \
        : "+f"((d)[0]), "+f"((d)[1]), "+f"((d)[2]), "+f"((d)[3]) \
        : "r"((a)[0]), "r"((a)[1]), "r"((a)[2]), "r"((a)[3]), \
          "r"((b)[0]), "r"((b)[1]))

#define SKS     72               // smem row stride in bf16 elems (144B, 16B-mult)

// ---------------------------------------------------------------------------
// Kernel 1: LoRA-A  Xa[m,r] = sum_e X[m,e] * la[r,e]
// ---------------------------------------------------------------------------
__global__ void lora_a_kernel(const float* __restrict__ X,
                              const float* __restrict__ la,
                              float* __restrict__ Xa) {
    int m = blockIdx.x;
    int t = threadIdx.x;          // 128
    int r  = t & 15;
    int eo = t >> 4;              // 0..7
    const float* x   = X  + (size_t)m * E_;
    const float* lar = la + (size_t)r * E_;
    float acc = 0.f;
    #pragma unroll 8
    for (int e = eo; e < E_; e += 8) acc += x[e] * lar[e];
    __shared__ float sm[16][8];
    sm[r][eo] = acc;
    __syncthreads();
    if (t < 16) {
        float s = 0.f;
        #pragma unroll
        for (int i = 0; i < 8; i++) s += sm[t][i];
        Xa[(size_t)m * R_ + t] = s;
    }
}

// ---------------------------------------------------------------------------
// Kernel 2: bf16 mma.sync (3-term hi/lo split) GEMM + LoRA + bias
// Output: either fp32 C, or bf16 hi/lo pair (for Q/K/V feeding attention mma)
// ---------------------------------------------------------------------------
#define GNC     17               // 16 K-chunks + 1 LoRA chunk
#define MAT_B   (128 * SKS * 2)  // one bf16 matrix buffer: 18432 B
#define SMEM_GEMM_TOTAL (8 * MAT_B + 512)

__device__ __forceinline__ void ldg_chunk(
    const float* __restrict__ A, const float* __restrict__ W,
    const float* __restrict__ Xa, const float* __restrict__ lb,
    int chunk, int m0, int n0, int tid, float* rA, float* rW)
{
    int r  = tid >> 1;            // 0..127
    int c0 = (tid & 1) * 32;      // 0 or 32
    if (chunk < 16) {
        const float* pa = A + (size_t)(m0 + r) * E_ + chunk * 64 + c0;
        const float* pw = W + (size_t)(n0 + r) * E_ + chunk * 64 + c0;
        #pragma unroll
        for (int i = 0; i < 8; i++) {
            float4 v = *(const float4*)(pa + i * 4);
            rA[4*i+0] = v.x; rA[4*i+1] = v.y; rA[4*i+2] = v.z; rA[4*i+3] = v.w;
            float4 w = *(const float4*)(pw + i * 4);
            rW[4*i+0] = w.x; rW[4*i+1] = w.y; rW[4*i+2] = w.z; rW[4*i+3] = w.w;
        }
    } else {
        #pragma unroll
        for (int i = 0; i < 32; i++) { rA[i] = 0.f; rW[i] = 0.f; }
        if (c0 == 0) {
            const float* px = Xa + (size_t)(m0 + r) * R_;
            const float* pl = lb + (size_t)(n0 + r) * R_;
            #pragma unroll
            for (int i = 0; i < 4; i++) {
                float4 v = *(const float4*)(px + i * 4);
                rA[4*i+0] = SCALING * v.x; rA[4*i+1] = SCALING * v.y;
                rA[4*i+2] = SCALING * v.z; rA[4*i+3] = SCALING * v.w;
                float4 w = *(const float4*)(pl + i * 4);
                rW[4*i+0] = w.x; rW[4*i+1] = w.y; rW[4*i+2] = w.z; rW[4*i+3] = w.w;
            }
        }
    }
}

__device__ __forceinline__ void split_pair(float f0, float f1,
                                           __nv_bfloat162* hi, __nv_bfloat162* lo) {
    __nv_bfloat16 h0 = __float2bfloat16_rn(f0);
    __nv_bfloat16 h1 = __float2bfloat16_rn(f1);
    __nv_bfloat16 l0 = __float2bfloat16_rn(f0 - __bfloat162float(h0));
    __nv_bfloat16 l1 = __float2bfloat16_rn(f1 - __bfloat162float(h1));
    *hi = __nv_bfloat162(h0, h1);
    *lo = __nv_bfloat162(l0, l1);
}

__device__ __forceinline__ void sts_chunk(
    char* sm, int buf, int tid, const float* rA, const float* rW)
{
    int r  = tid >> 1;
    int c0 = (tid & 1) * 32;
    __nv_bfloat16* Ahi = (__nv_bfloat16*)(sm + (buf * 4 + 0) * MAT_B);
    __nv_bfloat16* Alo = (__nv_bfloat16*)(sm + (buf * 4 + 1) * MAT_B);
    __nv_bfloat16* Whi = (__nv_bfloat16*)(sm + (buf * 4 + 2) * MAT_B);
    __nv_bfloat16* Wlo = (__nv_bfloat16*)(sm + (buf * 4 + 3) * MAT_B);
    #pragma unroll
    for (int p = 0; p < 16; p++) {
        int off = r * SKS + c0 + 2 * p;
        __nv_bfloat162 h, l;
        split_pair(rA[2*p], rA[2*p+1], &h, &l);
        *(__nv_bfloat162*)&Ahi[off] = h;
        *(__nv_bfloat162*)&Alo[off] = l;
        split_pair(rW[2*p], rW[2*p+1], &h, &l);
        *(__nv_bfloat162*)&Whi[off] = h;
        *(__nv_bfloat162*)&Wlo[off] = l;
    }
}

__global__ __launch_bounds__(256, 1)
void gemm_lora_mma(const float* __restrict__ A, const float* __restrict__ W,
                   const float* __restrict__ bias, const float* __restrict__ Xa,
                   const float* __restrict__ lb, float* __restrict__ C,
                   __nv_bfloat16* __restrict__ Chi, __nv_bfloat16* __restrict__ Clo)
{
    extern __shared__ char sm[];
    float* biasS = (float*)(sm + 8 * MAT_B);

    int tid = threadIdx.x;
    int wid = tid >> 5;
    int lane = tid & 31;
    int warp_m = wid >> 2;       // 0..1
    int warp_n = wid & 3;        // 0..3
    int m0 = blockIdx.y * 128;
    int n0 = blockIdx.x * 128;

    if (tid < 128) biasS[tid] = bias[n0 + tid];

    float acc[4][4][4];
    #pragma unroll
    for (int i = 0; i < 4; i++)
        #pragma unroll
        for (int j = 0; j < 4; j++)
            #pragma unroll
            for (int q = 0; q < 4; q++) acc[i][j][q] = 0.f;

    float rA[32], rW[32];
    ldg_chunk(A, W, Xa, lb, 0, m0, n0, tid, rA, rW);
    sts_chunk(sm, 0, tid, rA, rW);
    __syncthreads();

    int a_row = warp_m * 64 + (lane & 15);
    int a_colk = (lane >> 4) * 8;
    int b_row = warp_n * 32 + ((lane >> 4) << 3) + (lane & 7);
    int b_colk = ((lane >> 3) & 1) * 8;

    for (int c = 0; c < GNC; c++) {
        if (c + 1 < GNC) ldg_chunk(A, W, Xa, lb, c + 1, m0, n0, tid, rA, rW);

        int buf = c & 1;
        uint32_t sAhi = smem_u32(sm + (buf * 4 + 0) * MAT_B);
        uint32_t sAlo = smem_u32(sm + (buf * 4 + 1) * MAT_B);
        uint32_t sWhi = smem_u32(sm + (buf * 4 + 2) * MAT_B);
        uint32_t sWlo = smem_u32(sm + (buf * 4 + 3) * MAT_B);

        #pragma unroll
        for (int kk = 0; kk < 4; kk++) {
            int k0 = kk * 16;
            uint32_t ahi[4][4], alo[4][4];
            #pragma unroll
            for (int i = 0; i < 4; i++) {
                uint32_t off = (uint32_t)(((a_row + i * 16) * SKS) + k0 + a_colk) * 2;
                LDMATRIX_X4(ahi[i], sAhi + off);
                LDMATRIX_X4(alo[i], sAlo + off);
            }
            uint32_t bhi[4][2], blo[4][2];
            #pragma unroll
            for (int jp = 0; jp < 2; jp++) {
                uint32_t off = (uint32_t)(((b_row + jp * 16) * SKS) + k0 + b_colk) * 2;
                uint32_t t[4];
                LDMATRIX_X4(t, sWhi + off);
                bhi[jp*2][0] = t[0]; bhi[jp*2][1] = t[1];
                bhi[jp*2+1][0] = t[2]; bhi[jp*2+1][1] = t[3];
                LDMATRIX_X4(t, sWlo + off);
                blo[jp*2][0] = t[0]; blo[jp*2][1] = t[1];
                blo[jp*2+1][0] = t[2]; blo[jp*2+1][1] = t[3];
            }
            #pragma unroll
            for (int i = 0; i < 4; i++)
                #pragma unroll
                for (int j = 0; j < 4; j++) {
                    MMA_BF16(acc[i][j], ahi[i], bhi[j]);
                    MMA_BF16(acc[i][j], ahi[i], blo[j]);
                    MMA_BF16(acc[i][j], alo[i], bhi[j]);
                }
        }
        __syncthreads();
        if (c + 1 < GNC) {
            sts_chunk(sm, (c + 1) & 1, tid, rA, rW);
            __syncthreads();
        }
    }

    // epilogue
    int g  = lane >> 2;
    int tg = lane & 3;
    #pragma unroll
    for (int i = 0; i < 4; i++) {
        int row = m0 + warp_m * 64 + i * 16 + g;
        #pragma unroll
        for (int j = 0; j < 4; j++) {
            int colb = warp_n * 32 + j * 8 + 2 * tg;
            float b0 = biasS[colb], b1 = biasS[colb + 1];
            float v0 = acc[i][j][0] + b0, v1 = acc[i][j][1] + b1;
            float v2 = acc[i][j][2] + b0, v3 = acc[i][j][3] + b1;
            size_t o0 = (size_t)row * E_ + n0 + colb;
            size_t o1 = (size_t)(row + 8) * E_ + n0 + colb;
            if (Chi) {
                __nv_bfloat162 h, l;
                split_pair(v0, v1, &h, &l);
                *(__nv_bfloat162*)&Chi[o0] = h;
                *(__nv_bfloat162*)&Clo[o0] = l;
                split_pair(v2, v3, &h, &l);
                *(__nv_bfloat162*)&Chi[o1] = h;
                *(__nv_bfloat162*)&Clo[o1] = l;
            } else {
                *(float2*)&C[o0] = make_float2(v0, v1);
                *(float2*)&C[o1] = make_float2(v2, v3);
            }
        }
    }
}

// ---------------------------------------------------------------------------
// Kernel 3: scores via mma.sync.  P[bh,t,s] = 0.125 * sum_d Q.K
// 128x128 tile, K=64 staged once.  3-term hi/lo split.
// ---------------------------------------------------------------------------
#define SMEM_SCORES_TOTAL (4 * 128 * SKS * 2)   // 73728

__global__ __launch_bounds__(256, 1)
void scores_mma(const __nv_bfloat16* __restrict__ Qh, const __nv_bfloat16* __restrict__ Ql,
                const __nv_bfloat16* __restrict__ Kh, const __nv_bfloat16* __restrict__ Kl,
                float* __restrict__ P)
{
    extern __shared__ char smn[];
    __nv_bfloat16* sQh = (__nv_bfloat16*)smn;
    __nv_bfloat16* sQl = sQh + 128 * SKS;
    __nv_bfloat16* sKh = sQl + 128 * SKS;
    __nv_bfloat16* sKl = sKh + 128 * SKS;

    int bh = blockIdx.z;
    int b = bh >> 4, h = bh & 15;
    int t0 = blockIdx.y * 128;
    int s0 = blockIdx.x * 128;

    int tid = threadIdx.x;
    int wid = tid >> 5;
    int lane = tid & 31;
    int warp_m = wid >> 2;
    int warp_n = wid & 3;

    // stage Q/K hi+lo tiles: each thread loads 32 bf16 (4x uint4) per matrix
    {
        int row = tid >> 1, half = tid & 1;
        size_t qoff = ((size_t)(t0 + row) * B_ + b) * E_ + h * HD_ + half * 32;
        size_t koff = ((size_t)(s0 + row) * B_ + b) * E_ + h * HD_ + half * 32;
        int d = row * SKS + half * 32;
        #pragma unroll
        for (int i = 0; i < 4; i++) {
            *(uint4*)&sQh[d + i * 8] = *(const uint4*)&Qh[qoff + i * 8];
            *(uint4*)&sQl[d + i * 8] = *(const uint4*)&Ql[qoff + i * 8];
            *(uint4*)&sKh[d + i * 8] = *(const uint4*)&Kh[koff + i * 8];
            *(uint4*)&sKl[d + i * 8] = *(const uint4*)&Kl[koff + i * 8];
        }
    }
    __syncthreads();

    float acc[4][4][4];
    #pragma unroll
    for (int i = 0; i < 4; i++)
        #pragma unroll
        for (int j = 0; j < 4; j++)
            #pragma unroll
            for (int q = 0; q < 4; q++) acc[i][j][q] = 0.f;

    int a_row = warp_m * 64 + (lane & 15);
    int a_colk = (lane >> 4) * 8;
    int b_row = warp_n * 32 + ((lane >> 4) << 3) + (lane & 7);
    int b_colk = ((lane >> 3) & 1) * 8;

    uint32_t uQh = smem_u32(sQh), uQl = smem_u32(sQl);
    uint32_t uKh = smem_u32(sKh), uKl = smem_u32(sKl);

    #pragma unroll
    for (int kk = 0; kk < 4; kk++) {
        int k0 = kk * 16;
        uint32_t ahi[4][4], alo[4][4];
        #pragma unroll
        for (int i = 0; i < 4; i++) {
            uint32_t off = (uint32_t)(((a_row + i * 16) * SKS) + k0 + a_colk) * 2;
            LDMATRIX_X4(ahi[i], uQh + off);
            LDMATRIX_X4(alo[i], uQl + off);
        }
        uint32_t bhi[4][2], blo[4][2];
        #pragma unroll
        for (int jp = 0; jp < 2; jp++) {
            uint32_t off = (uint32_t)(((b_row + jp * 16) * SKS) + k0 + b_colk) * 2;
            uint32_t t[4];
            LDMATRIX_X4(t, uKh + off);
            bhi[jp*2][0] = t[0]; bhi[jp*2][1] = t[1];
            bhi[jp*2+1][0] = t[2]; bhi[jp*2+1][1] = t[3];
            LDMATRIX_X4(t, uKl + off);
            blo[jp*2][0] = t[0]; blo[jp*2][1] = t[1];
            blo[jp*2+1][0] = t[2]; blo[jp*2+1][1] = t[3];
        }
        #pragma unroll
        for (int i = 0; i < 4; i++)
            #pragma unroll
            for (int j = 0; j < 4; j++) {
                MMA_BF16(acc[i][j], ahi[i], bhi[j]);
                MMA_BF16(acc[i][j], ahi[i], blo[j]);
                MMA_BF16(acc[i][j], alo[i], bhi[j]);
            }
    }

    // epilogue: scale + store
    const float scale = 0.125f;
    size_t base = (size_t)bh * T_ * S_;
    int g  = lane >> 2;
    int tg = lane & 3;
    #pragma unroll
    for (int i = 0; i < 4; i++) {
        int row = t0 + warp_m * 64 + i * 16 + g;
        #pragma unroll
        for (int j = 0; j < 4; j++) {
            int colb = s0 + warp_n * 32 + j * 8 + 2 * tg;
            *(float2*)&P[base + (size_t)row * S_ + colb] =
                make_float2(acc[i][j][0] * scale, acc[i][j][1] * scale);
            *(float2*)&P[base + (size_t)(row + 8) * S_ + colb] =
                make_float2(acc[i][j][2] * scale, acc[i][j][3] * scale);
        }
    }
}

// ---------------------------------------------------------------------------
// Kernel 4: fused row softmax (in place) + head-mean attn_w
// One block per (b,t); loops over 16 heads.
// ---------------------------------------------------------------------------
__global__ __launch_bounds__(256)
void softmax_attnw(float* __restrict__ P, float* __restrict__ Wout, int do_w) {
    int bx = blockIdx.x;
    int b = bx >> 11;              // T_=2048
    int t = bx & (T_ - 1);
    int tid = threadIdx.x;
    __shared__ float red[8];

    float wacc[8];
    #pragma unroll
    for (int i = 0; i < 8; i++) wacc[i] = 0.f;

    for (int h = 0; h < H_; h++) {
        float* p = P + ((size_t)(b * H_ + h) * T_ + t) * S_;
        float v[8];
        float mx = -1e30f;
        #pragma unroll
        for (int i = 0; i < 8; i++) {
            v[i] = p[tid + i * 256];
            mx = fmaxf(mx, v[i]);
        }
        #pragma unroll
        for (int o = 16; o; o >>= 1) mx = fmaxf(mx, __shfl_xor_sync(~0u, mx, o));
        if ((tid & 31) == 0) red[tid >> 5] = mx;
        __syncthreads();
        mx = red[0];
        #pragma unroll
        for (int i = 1; i < 8; i++) mx = fmaxf(mx, red[i]);
        __syncthreads();

        float sum = 0.f;
        #pragma unroll
        for (int i = 0; i < 8; i++) {
            v[i] = __expf(v[i] - mx);
            sum += v[i];
        }
        #pragma unroll
        for (int o = 16; o; o >>= 1) sum += __shfl_xor_sync(~0u, sum, o);
        if ((tid & 31) == 0) red[tid >> 5] = sum;
        __syncthreads();
        sum = 0.f;
        #pragma unroll
        for (int i = 0; i < 8; i++) sum += red[i];
        float inv = 1.0f / sum;
        #pragma unroll
        for (int i = 0; i < 8; i++) {
            float pr = v[i] * inv;
            p[tid + i * 256] = pr;
            wacc[i] += pr;
        }
        __syncthreads();   // red[] reused next head
    }

    if (do_w) {
        float* w = Wout + ((size_t)b * T_ + t) * S_;
        #pragma unroll
        for (int i = 0; i < 8; i++) w[tid + i * 256] = wacc[i] * (1.0f / H_);
    }
}

// ---------------------------------------------------------------------------
// Kernel 5: PV via mma.sync.  O[t, h*64+d] = sum_s P[bh,t,s] * V[s, h*64+d]
// Tile: 128 t x 64 d per CTA, k-chunks of 64 s.  A = Phi (bf16 of fp32 P),
// B = V hi/lo via ldmatrix.trans.  2 terms: Phi*Vhi + Phi*Vlo.
// ---------------------------------------------------------------------------
__global__ __launch_bounds__(256, 1)
void pv_mma(const float* __restrict__ P,
            const __nv_bfloat16* __restrict__ Vh, const __nv_bfloat16* __restrict__ Vl,
            float* __restrict__ O)
{
    __shared__ __nv_bfloat16 sP[128 * SKS];
    __shared__ __nv_bfloat16 sVh[64 * SKS];
    __shared__ __nv_bfloat16 sVl[64 * SKS];

    int bh = blockIdx.y;
    int b = bh >> 4, h = bh & 15;
    int t0 = blockIdx.x * 128;

    int tid = threadIdx.x;
    int wid = tid >> 5;
    int lane = tid & 31;
    int warp_m = wid >> 1;       // 0..3  (32 t rows each)
    int warp_n = wid & 1;        // 0..1  (32 d cols each)

    float acc[2][4][4];
    #pragma unroll
    for (int i = 0; i < 2; i++)
        #pragma unroll
        for (int j = 0; j < 4; j++)
            #pragma unroll
            for (int q = 0; q < 4; q++) acc[i][j][q] = 0.f;

    int a_row = warp_m * 32 + (lane & 15);
    int a_colk = (lane >> 4) * 8;
    // ldmatrix.trans lane addressing for B (V stored [s][d] row-major)
    int sub = lane >> 3;
    int tr_row = (sub & 1) * 8 + (lane & 7);
    int tr_col = (sub >> 1) * 8;

    // load-task mapping
    int prow = tid >> 1, phalf = tid & 1;                 // P tile: 128 rows x 2 halves
    int vmat = tid >> 7, vrem = tid & 127;                // V: 2 matrices
    int vrow = vrem >> 1, vhalf = vrem & 1;

    size_t pbase = ((size_t)bh * T_ + t0 + prow) * S_ + phalf * 32;

    for (int k0 = 0; k0 < S_; k0 += 64) {
        // P tile -> bf16 (hi only)
        {
            const float* src = P + pbase + k0;
            int d = prow * SKS + phalf * 32;
            #pragma unroll
            for (int i = 0; i < 8; i++) {
                float4 v = *(const float4*)(src + i * 4);
                *(__nv_bfloat162*)&sP[d + i * 4]     =
                    __nv_bfloat162(__float2bfloat16_rn(v.x), __float2bfloat16_rn(v.y));
                *(__nv_bfloat162*)&sP[d + i * 4 + 2] =
                    __nv_bfloat162(__float2bfloat16_rn(v.z), __float2bfloat16_rn(v.w));
            }
        }
        // V chunk [64 s][64 d] hi+lo
        {
            const __nv_bfloat16* src = (vmat ? Vl : Vh) +
                ((size_t)(k0 + vrow) * B_ + b) * E_ + h * HD_ + vhalf * 32;
            __nv_bfloat16* dst = (vmat ? sVl : sVh) + vrow * SKS + vhalf * 32;
            #pragma unroll
            for (int i = 0; i < 4; i++)
                *(uint4*)&dst[i * 8] = *(const uint4*)&src[i * 8];
        }
        __syncthreads();

        uint32_t uP = smem_u32(sP), uVh = smem_u32(sVh), uVl = smem_u32(sVl);
        #pragma unroll
        for (int kk = 0; kk < 4; kk++) {
            uint32_t a[2][4];
            #pragma unroll
            for (int i = 0; i < 2; i++) {
                uint32_t off = (uint32_t)(((a_row + i * 16) * SKS) + kk * 16 + a_colk) * 2;
                LDMATRIX_X4(a[i], uP + off);
            }
            uint32_t bhv[4][2], blv[4][2];
            #pragma unroll
            for (int j2 = 0; j2 < 2; j2++) {
                uint32_t off = (uint32_t)(((kk * 16 + tr_row) * SKS) +
                                          warp_n * 32 + j2 * 16 + tr_col) * 2;
                uint32_t t[4];
                LDMATRIX_X4_T(t, uVh + off);
                bhv[j2*2][0] = t[0]; bhv[j2*2][1] = t[1];
                bhv[j2*2+1][0] = t[2]; bhv[j2*2+1][1] = t[3];
                LDMATRIX_X4_T(t, uVl + off);
                blv[j2*2][0] = t[0]; blv[j2*2][1] = t[1];
                blv[j2*2+1][0] = t[2]; blv[j2*2+1][1] = t[3];
            }
            #pragma unroll
            for (int i = 0; i < 2; i++)
                #pragma unroll
                for (int j = 0; j < 4; j++) {
                    MMA_BF16(acc[i][j], a[i], bhv[j]);
                    MMA_BF16(acc[i][j], a[i], blv[j]);
                }
        }
        __syncthreads();
    }

    // epilogue: fp32 O
    int g  = lane >> 2;
    int tg = lane & 3;
    #pragma unroll
    for (int i = 0; i < 2; i++) {
        int trow = t0 + warp_m * 32 + i * 16 + g;
        #pragma unroll
        for (int j = 0; j < 4; j++) {
            int col = h * HD_ + warp_n * 32 + j * 8 + 2 * tg;
            size_t o0 = ((size_t)trow * B_ + b) * E_ + col;
            size_t o1 = ((size_t)(trow + 8) * B_ + b) * E_ + col;
            *(float2*)&O[o0] = make_float2(acc[i][j][0], acc[i][j][1]);
            *(float2*)&O[o1] = make_float2(acc[i][j][2], acc[i][j][3]);
        }
    }
}

// ---------------------------------------------------------------------------
// Host launcher
// ---------------------------------------------------------------------------
extern "C" void kernel_launch(void* const* d_in, const int* in_sizes, int n_in,
                              void* d_out, int out_size) {
    const float* query = (const float*)d_in[0];
    const float* key   = (const float*)d_in[1];
    const float* value = (const float*)d_in[2];
    const float* q_w  = (const float*)d_in[3];
    const float* q_b  = (const float*)d_in[4];
    const float* q_la = (const float*)d_in[5];
    const float* q_lb = (const float*)d_in[6];
    const float* k_w  = (const float*)d_in[7];
    const float* k_b  = (const float*)d_in[8];
    const float* k_la = (const float*)d_in[9];
    const float* k_lb = (const float*)d_in[10];
    const float* v_w  = (const float*)d_in[11];
    const float* v_b  = (const float*)d_in[12];
    const float* v_la = (const float*)d_in[13];
    const float* v_lb = (const float*)d_in[14];
    const float* o_w  = (const float*)d_in[15];
    const float* o_b  = (const float*)d_in[16];
    const float* o_la = (const float*)d_in[17];
    const float* o_lb = (const float*)d_in[18];

    float *O, *P, *Xa;
    __nv_bfloat16 *Qh, *Ql, *Kh, *Kl, *Vh, *Vl;
    cudaGetSymbolAddress((void**)&O,  g_O);
    cudaGetSymbolAddress((void**)&P,  g_P);
    cudaGetSymbolAddress((void**)&Xa, g_Xa);
    cudaGetSymbolAddress((void**)&Qh, g_Qh);
    cudaGetSymbolAddress((void**)&Ql, g_Ql);
    cudaGetSymbolAddress((void**)&Kh, g_Kh);
    cudaGetSymbolAddress((void**)&Kl, g_Kl);
    cudaGetSymbolAddress((void**)&Vh, g_Vh);
    cudaGetSymbolAddress((void**)&Vl, g_Vl);
    float* XaQ = Xa;
    float* XaK = Xa + (size_t)M_ * R_;
    float* XaV = Xa + 2 * (size_t)M_ * R_;
    float* XaO = Xa + 3 * (size_t)M_ * R_;

    float* out1 = (float*)d_out;
    bool write_attnw = ((size_t)out_size >= OUT1_ELEMS + OUT2_ELEMS);
    float* out2 = out1 + OUT1_ELEMS;

    cudaFuncSetAttribute(gemm_lora_mma, cudaFuncAttributeMaxDynamicSharedMemorySize,
                         SMEM_GEMM_TOTAL);
    cudaFuncSetAttribute(scores_mma, cudaFuncAttributeMaxDynamicSharedMemorySize,
                         SMEM_SCORES_TOTAL);

    dim3 gGemm(E_ / 128, M_ / 128);      // (8, 32)

    // LoRA-A for q,k,v
    lora_a_kernel<<<M_, 128>>>(query, q_la, XaQ);
    lora_a_kernel<<<M_, 128>>>(key,   k_la, XaK);
    lora_a_kernel<<<M_, 128>>>(value, v_la, XaV);

    // projections -> bf16 hi/lo
    gemm_lora_mma<<<gGemm, 256, SMEM_GEMM_TOTAL>>>(query, q_w, q_b, XaQ, q_lb,
                                                   nullptr, Qh, Ql);
    gemm_lora_mma<<<gGemm, 256, SMEM_GEMM_TOTAL>>>(key,   k_w, k_b, XaK, k_lb,
                                                   nullptr, Kh, Kl);
    gemm_lora_mma<<<gGemm, 256, SMEM_GEMM_TOTAL>>>(value, v_w, v_b, XaV, v_lb,
                                                   nullptr, Vh, Vl);

    // scores (tensor cores)
    dim3 gScores(S_ / 128, T_ / 128, BH_);   // (16,16,32)
    scores_mma<<<gScores, 256, SMEM_SCORES_TOTAL>>>(Qh, Ql, Kh, Kl, P);

    // fused softmax + attn_w mean
    softmax_attnw<<<B_ * T_, 256>>>(P, out2, write_attnw ? 1 : 0);

    // P @ V (tensor cores)
    dim3 gPV(T_ / 128, BH_);                 // (16, 32)
    pv_mma<<<gPV, 256>>>(P, Vh, Vl, O);

    // output projection (fp32 out)
    lora_a_kernel<<<M_, 128>>>(O, o_la, XaO);
    gemm_lora_mma<<<gGemm, 256, SMEM_GEMM_TOTAL>>>(O, o_w, o_b, XaO, o_lb,
                                                   out1, nullptr, nullptr);
}

// round 9
// speedup vs baseline: 1.7162x; 1.7162x over previous
#include <cuda_runtime.h>
#include <cuda_bf16.h>
#include <cstdint>
#include <math.h>

// Problem constants
#define T_  2048
#define B_  2
#define S_  2048
#define E_  1024
#define H_  16
#define HD_ 64
#define R_  16
#define M_  (T_ * B_)
#define BH_ (B_ * H_)
#define SCALING 1.0f
#define OUT1_ELEMS ((size_t)T_ * B_ * E_)
#define OUT2_ELEMS ((size_t)B_ * T_ * S_)

// ---------------------------------------------------------------------------
// Static device scratch
// ---------------------------------------------------------------------------
__device__ float g_O[M_ * E_];                         // attention out (fp32)
__device__ float g_P[(size_t)BH_ * T_ * S_];           // fp32 logits (512MB)
__device__ __nv_bfloat16 g_Ph[(size_t)BH_ * T_ * S_];  // probs hi (256MB)
__device__ __nv_bfloat16 g_Pl[(size_t)BH_ * T_ * S_];  // probs lo (256MB)
__device__ __nv_bfloat16 g_Qh[M_ * E_], g_Ql[M_ * E_]; // head-major [bh][t][64]
__device__ __nv_bfloat16 g_Kh[M_ * E_], g_Kl[M_ * E_];
__device__ __nv_bfloat16 g_Vh[M_ * E_], g_Vl[M_ * E_];
__device__ __nv_bfloat16 g_Ah[M_ * E_], g_Al[M_ * E_]; // pre-split gemm A (reused)
__device__ __nv_bfloat16 g_Wh[E_ * E_], g_Wl[E_ * E_]; // pre-split weights (reused)
__device__ __nv_bfloat16 g_lbh[E_ * 32], g_lbl[E_ * 32];   // padded LoRA-B (reused)
__device__ __nv_bfloat16 g_Xah[4 * M_ * 32], g_Xal[4 * M_ * 32]; // padded LoRA-A

// ---------------------------------------------------------------------------
// PTX helpers
// ---------------------------------------------------------------------------
__device__ __forceinline__ uint32_t smem_u32(const void* p) {
    uint32_t a;
    asm("{ .reg .u64 t; cvta.to.shared.u64 t, %1; cvt.u32.u64 %0, t; }" : "=r"(a) : "l"(p));
    return a;
}
#define LDMATRIX_X4(r, addr) \
    asm volatile("ldmatrix.sync.aligned.m8n8.x4.shared.b16 {%0,%1,%2,%3}, [%4];" \
        : "=r"((r)[0]), "=r"((r)[1]), "=r"((r)[2]), "=r"((r)[3]) : "r"(addr))
#define LDMATRIX_X4_T(r, addr) \
    asm volatile("ldmatrix.sync.aligned.m8n8.x4.trans.shared.b16 {%0,%1,%2,%3}, [%4];" \
        : "=r"((r)[0]), "=r"((r)[1]), "=r"((r)[2]), "=r"((r)[3]) : "r"(addr))
#define MMA_BF16(d, a, b) \
    asm volatile("mma.sync.aligned.m16n8k16.row.col.f32.bf16.bf16.f32 " \
        "{%0,%1,%2,%3}, {%4,%5,%6,%7}, {%8,%9}, {%0,%1,%2,%3};" \
        : "+f"((d)[0]), "+f"((d)[1]), "+f"((d)[2]), "+f"((d)[3]) \
        : "r"((a)[0]), "r"((a)[1]), "r"((a)[2]), "r"((a)[3]), \
          "r"((b)[0]), "r"((b)[1]))
#define CP16(dst, src) \
    asm volatile("cp.async.cg.shared.global [%0], [%1], 16;" :: "r"(dst), "l"(src))
#define CP_COMMIT() asm volatile("cp.async.commit_group;")
#define CP_WAIT0()  asm volatile("cp.async.wait_group 0;" ::: "memory")
#define CP_WAIT1()  asm volatile("cp.async.wait_group 1;" ::: "memory")

__device__ __forceinline__ void split_pair(float f0, float f1,
                                           __nv_bfloat162* hi, __nv_bfloat162* lo) {
    __nv_bfloat16 h0 = __float2bfloat16_rn(f0);
    __nv_bfloat16 h1 = __float2bfloat16_rn(f1);
    __nv_bfloat16 l0 = __float2bfloat16_rn(f0 - __bfloat162float(h0));
    __nv_bfloat16 l1 = __float2bfloat16_rn(f1 - __bfloat162float(h1));
    *hi = __nv_bfloat162(h0, h1);
    *lo = __nv_bfloat162(l0, l1);
}

// ---------------------------------------------------------------------------
// Split kernels (one-time fp32 -> bf16 hi/lo)
// ---------------------------------------------------------------------------
__global__ void split_mat(const float* __restrict__ X,
                          __nv_bfloat16* __restrict__ Xh,
                          __nv_bfloat16* __restrict__ Xl, int n4) {
    int i = blockIdx.x * blockDim.x + threadIdx.x;
    if (i >= n4) return;
    float4 v = ((const float4*)X)[i];
    __nv_bfloat162 h0, l0, h1, l1;
    split_pair(v.x, v.y, &h0, &l0);
    split_pair(v.z, v.w, &h1, &l1);
    ((__nv_bfloat162*)Xh)[2 * i]     = h0;
    ((__nv_bfloat162*)Xh)[2 * i + 1] = h1;
    ((__nv_bfloat162*)Xl)[2 * i]     = l0;
    ((__nv_bfloat162*)Xl)[2 * i + 1] = l1;
}

__global__ void split_lb(const float* __restrict__ lb,
                         __nv_bfloat16* __restrict__ lbh,
                         __nv_bfloat16* __restrict__ lbl) {
    int r = blockIdx.x * blockDim.x + threadIdx.x;
    if (r >= E_) return;
    #pragma unroll
    for (int j = 0; j < 16; j += 2) {
        __nv_bfloat162 h, l;
        split_pair(lb[r * R_ + j], lb[r * R_ + j + 1], &h, &l);
        *(__nv_bfloat162*)&lbh[r * 32 + j] = h;
        *(__nv_bfloat162*)&lbl[r * 32 + j] = l;
    }
    __nv_bfloat162 z = __nv_bfloat162(__float2bfloat16_rn(0.f), __float2bfloat16_rn(0.f));
    #pragma unroll
    for (int j = 16; j < 32; j += 2) {
        *(__nv_bfloat162*)&lbh[r * 32 + j] = z;
        *(__nv_bfloat162*)&lbl[r * 32 + j] = z;
    }
}

// ---------------------------------------------------------------------------
// LoRA-A: Xa[m,r] = SCALING * sum_e X[m,e]*la[r,e], written padded bf16 hi/lo
// ---------------------------------------------------------------------------
__global__ void lora_a2(const float* __restrict__ X, const float* __restrict__ la,
                        __nv_bfloat16* __restrict__ Xah, __nv_bfloat16* __restrict__ Xal) {
    int m = blockIdx.x;
    int t = threadIdx.x;          // 128
    int r  = t & 15;
    int eo = t >> 4;
    const float* x   = X  + (size_t)m * E_;
    const float* lar = la + (size_t)r * E_;
    float acc = 0.f;
    #pragma unroll 8
    for (int e = eo; e < E_; e += 8) acc += x[e] * lar[e];
    __shared__ float sm[16][8];
    sm[r][eo] = acc;
    __syncthreads();
    if (t < 16) {
        float s = 0.f;
        #pragma unroll
        for (int i = 0; i < 8; i++) s += sm[t][i];
        s *= SCALING;
        __nv_bfloat16 h = __float2bfloat16_rn(s);
        __nv_bfloat16 l = __float2bfloat16_rn(s - __bfloat162float(h));
        Xah[(size_t)m * 32 + t] = h;
        Xal[(size_t)m * 32 + t] = l;
    } else if (t < 32) {
        Xah[(size_t)m * 32 + t] = __float2bfloat16_rn(0.f);
        Xal[(size_t)m * 32 + t] = __float2bfloat16_rn(0.f);
    }
}

// ---------------------------------------------------------------------------
// GEMM: C = A@W^T + bias + LoRA, cp.async double-buffered, pre-split bf16 in.
// Tile 128x128, BK=32, 33 chunks (chunk 32 = padded LoRA).
// ---------------------------------------------------------------------------
#define SK2   40                    // smem row stride (bf16): 80B
#define MB2   (128 * SK2 * 2)       // 10240 B
#define NCH   33
#define SMEM_G2 (8 * MB2 + 512)     // 82432

__device__ __forceinline__ void g2_issue(
    const __nv_bfloat16* Ah, const __nv_bfloat16* Al,
    const __nv_bfloat16* Wh, const __nv_bfloat16* Wl,
    const __nv_bfloat16* Xah, const __nv_bfloat16* Xal,
    const __nv_bfloat16* lbh, const __nv_bfloat16* lbl,
    uint32_t smb, int buf, int chunk, int m0, int n0, int tid)
{
    // 4 matrices x 128 rows x 32 cols = 2048 x 16B segments, 8 per thread
    #pragma unroll
    for (int i = 0; i < 8; i++) {
        int u = tid + 256 * i;        // 0..2047
        int mat = u >> 9;             // 0 Ah, 1 Al, 2 Wh, 3 Wl
        int rem = u & 511;
        int row = rem >> 2;           // 0..127
        int seg = rem & 3;            // 0..3 (32 cols)
        uint32_t dst = smb + (uint32_t)(buf * 4 + mat) * MB2 + (uint32_t)(row * SK2 + seg * 8) * 2;
        const __nv_bfloat16* src;
        if (chunk < 32) {
            size_t off = (mat < 2)
                ? (size_t)(m0 + row) * E_ + chunk * 32 + seg * 8
                : (size_t)(n0 + row) * E_ + chunk * 32 + seg * 8;
            src = (mat == 0 ? Ah : mat == 1 ? Al : mat == 2 ? Wh : Wl) + off;
        } else {
            size_t off = (mat < 2)
                ? (size_t)(m0 + row) * 32 + seg * 8
                : (size_t)(n0 + row) * 32 + seg * 8;
            src = (mat == 0 ? Xah : mat == 1 ? Xal : mat == 2 ? lbh : lbl) + off;
        }
        CP16(dst, src);
    }
}

__global__ __launch_bounds__(256)
void gemm2(const __nv_bfloat16* __restrict__ Ah, const __nv_bfloat16* __restrict__ Al,
           const __nv_bfloat16* __restrict__ Wh, const __nv_bfloat16* __restrict__ Wl,
           const float* __restrict__ bias,
           const __nv_bfloat16* __restrict__ Xah, const __nv_bfloat16* __restrict__ Xal,
           const __nv_bfloat16* __restrict__ lbh, const __nv_bfloat16* __restrict__ lbl,
           float* __restrict__ C,
           __nv_bfloat16* __restrict__ Chi, __nv_bfloat16* __restrict__ Clo)
{
    extern __shared__ char sm[];
    uint32_t smb = smem_u32(sm);
    float* biasS = (float*)(sm + 8 * MB2);

    int tid = threadIdx.x;
    int wid = tid >> 5;
    int lane = tid & 31;
    int warp_m = wid >> 2;
    int warp_n = wid & 3;
    int m0 = blockIdx.y * 128;
    int n0 = blockIdx.x * 128;

    if (tid < 128) biasS[tid] = bias[n0 + tid];

    float acc[4][4][4];
    #pragma unroll
    for (int i = 0; i < 4; i++)
        #pragma unroll
        for (int j = 0; j < 4; j++)
            #pragma unroll
            for (int q = 0; q < 4; q++) acc[i][j][q] = 0.f;

    g2_issue(Ah, Al, Wh, Wl, Xah, Xal, lbh, lbl, smb, 0, 0, m0, n0, tid);
    CP_COMMIT();

    int a_row = warp_m * 64 + (lane & 15);
    int a_colk = (lane >> 4) * 8;
    int b_row = warp_n * 32 + ((lane >> 4) << 3) + (lane & 7);
    int b_colk = ((lane >> 3) & 1) * 8;

    for (int c = 0; c < NCH; c++) {
        if (c + 1 < NCH) {
            g2_issue(Ah, Al, Wh, Wl, Xah, Xal, lbh, lbl, smb, (c + 1) & 1, c + 1, m0, n0, tid);
            CP_COMMIT();
            CP_WAIT1();
        } else {
            CP_WAIT0();
        }
        __syncthreads();

        int buf = c & 1;
        uint32_t sAh = smb + (uint32_t)(buf * 4 + 0) * MB2;
        uint32_t sAl = smb + (uint32_t)(buf * 4 + 1) * MB2;
        uint32_t sWh = smb + (uint32_t)(buf * 4 + 2) * MB2;
        uint32_t sWl = smb + (uint32_t)(buf * 4 + 3) * MB2;

        #pragma unroll
        for (int kk = 0; kk < 2; kk++) {
            int k0 = kk * 16;
            uint32_t ahi[4][4], alo[4][4];
            #pragma unroll
            for (int i = 0; i < 4; i++) {
                uint32_t off = (uint32_t)(((a_row + i * 16) * SK2) + k0 + a_colk) * 2;
                LDMATRIX_X4(ahi[i], sAh + off);
                LDMATRIX_X4(alo[i], sAl + off);
            }
            uint32_t bhi[4][2], blo[4][2];
            #pragma unroll
            for (int jp = 0; jp < 2; jp++) {
                uint32_t off = (uint32_t)(((b_row + jp * 16) * SK2) + k0 + b_colk) * 2;
                uint32_t t[4];
                LDMATRIX_X4(t, sWh + off);
                bhi[jp*2][0] = t[0]; bhi[jp*2][1] = t[1];
                bhi[jp*2+1][0] = t[2]; bhi[jp*2+1][1] = t[3];
                LDMATRIX_X4(t, sWl + off);
                blo[jp*2][0] = t[0]; blo[jp*2][1] = t[1];
                blo[jp*2+1][0] = t[2]; blo[jp*2+1][1] = t[3];
            }
            #pragma unroll
            for (int i = 0; i < 4; i++)
                #pragma unroll
                for (int j = 0; j < 4; j++) {
                    MMA_BF16(acc[i][j], ahi[i], bhi[j]);
                    MMA_BF16(acc[i][j], ahi[i], blo[j]);
                    MMA_BF16(acc[i][j], alo[i], bhi[j]);
                }
        }
        __syncthreads();
    }

    // epilogue
    int g  = lane >> 2;
    int tg = lane & 3;
    #pragma unroll
    for (int i = 0; i < 4; i++) {
        int row = m0 + warp_m * 64 + i * 16 + g;
        #pragma unroll
        for (int j = 0; j < 4; j++) {
            int colb = warp_n * 32 + j * 8 + 2 * tg;
            float b0 = biasS[colb], b1 = biasS[colb + 1];
            float v0 = acc[i][j][0] + b0, v1 = acc[i][j][1] + b1;
            float v2 = acc[i][j][2] + b0, v3 = acc[i][j][3] + b1;
            if (Chi) {
                // head-major: m = t*B+b ; n = h*64+d -> [(b*H+h)*T + t]*64 + d
                int n = n0 + colb;
                int h = n >> 6, d = n & 63;
                int m0r = row, m1r = row + 8;
                size_t o0 = ((size_t)((m0r & 1) * H_ + h) * T_ + (m0r >> 1)) * HD_ + d;
                size_t o1 = ((size_t)((m1r & 1) * H_ + h) * T_ + (m1r >> 1)) * HD_ + d;
                __nv_bfloat162 hh, ll;
                split_pair(v0, v1, &hh, &ll);
                *(__nv_bfloat162*)&Chi[o0] = hh;
                *(__nv_bfloat162*)&Clo[o0] = ll;
                split_pair(v2, v3, &hh, &ll);
                *(__nv_bfloat162*)&Chi[o1] = hh;
                *(__nv_bfloat162*)&Clo[o1] = ll;
            } else {
                size_t o0 = (size_t)row * E_ + n0 + colb;
                size_t o1 = (size_t)(row + 8) * E_ + n0 + colb;
                *(float2*)&C[o0] = make_float2(v0, v1);
                *(float2*)&C[o1] = make_float2(v2, v3);
            }
        }
    }
}

// ---------------------------------------------------------------------------
// scores: P[bh,t,s] = 0.125 * sum_d Q.K ; 128x128 tile, head-major bf16 in.
// ---------------------------------------------------------------------------
#define SKS   72
#define MSC   (128 * SKS * 2)       // 18432
#define SMEM_SC (4 * MSC)           // 73728

__global__ __launch_bounds__(256)
void scores_mma(const __nv_bfloat16* __restrict__ Qh, const __nv_bfloat16* __restrict__ Ql,
                const __nv_bfloat16* __restrict__ Kh, const __nv_bfloat16* __restrict__ Kl,
                float* __restrict__ P)
{
    extern __shared__ char smn[];
    uint32_t smb = smem_u32(smn);

    int bh = blockIdx.z;
    int t0 = blockIdx.y * 128;
    int s0 = blockIdx.x * 128;
    int tid = threadIdx.x;
    int wid = tid >> 5;
    int lane = tid & 31;
    int warp_m = wid >> 2;
    int warp_n = wid & 3;

    // stage 4 tiles (128 rows x 64 cols each) = 4096 x 16B segments, 16/thread
    #pragma unroll
    for (int i = 0; i < 16; i++) {
        int u = tid + 256 * i;        // 0..4095
        int mat = u >> 10;            // 0 Qh, 1 Ql, 2 Kh, 3 Kl
        int rem = u & 1023;
        int row = rem >> 3;           // 0..127
        int seg = rem & 7;            // 0..7 (64 cols)
        uint32_t dst = smb + (uint32_t)mat * MSC + (uint32_t)(row * SKS + seg * 8) * 2;
        const __nv_bfloat16* base = (mat == 0 ? Qh : mat == 1 ? Ql : mat == 2 ? Kh : Kl);
        int r0 = (mat < 2) ? t0 : s0;
        CP16(dst, base + ((size_t)bh * T_ + r0 + row) * HD_ + seg * 8);
    }
    CP_COMMIT();
    CP_WAIT0();
    __syncthreads();

    float acc[4][4][4];
    #pragma unroll
    for (int i = 0; i < 4; i++)
        #pragma unroll
        for (int j = 0; j < 4; j++)
            #pragma unroll
            for (int q = 0; q < 4; q++) acc[i][j][q] = 0.f;

    int a_row = warp_m * 64 + (lane & 15);
    int a_colk = (lane >> 4) * 8;
    int b_row = warp_n * 32 + ((lane >> 4) << 3) + (lane & 7);
    int b_colk = ((lane >> 3) & 1) * 8;
    uint32_t uQh = smb, uQl = smb + MSC, uKh = smb + 2 * MSC, uKl = smb + 3 * MSC;

    #pragma unroll
    for (int kk = 0; kk < 4; kk++) {
        int k0 = kk * 16;
        uint32_t ahi[4][4], alo[4][4];
        #pragma unroll
        for (int i = 0; i < 4; i++) {
            uint32_t off = (uint32_t)(((a_row + i * 16) * SKS) + k0 + a_colk) * 2;
            LDMATRIX_X4(ahi[i], uQh + off);
            LDMATRIX_X4(alo[i], uQl + off);
        }
        uint32_t bhi[4][2], blo[4][2];
        #pragma unroll
        for (int jp = 0; jp < 2; jp++) {
            uint32_t off = (uint32_t)(((b_row + jp * 16) * SKS) + k0 + b_colk) * 2;
            uint32_t t[4];
            LDMATRIX_X4(t, uKh + off);
            bhi[jp*2][0] = t[0]; bhi[jp*2][1] = t[1];
            bhi[jp*2+1][0] = t[2]; bhi[jp*2+1][1] = t[3];
            LDMATRIX_X4(t, uKl + off);
            blo[jp*2][0] = t[0]; blo[jp*2][1] = t[1];
            blo[jp*2+1][0] = t[2]; blo[jp*2+1][1] = t[3];
        }
        #pragma unroll
        for (int i = 0; i < 4; i++)
            #pragma unroll
            for (int j = 0; j < 4; j++) {
                MMA_BF16(acc[i][j], ahi[i], bhi[j]);
                MMA_BF16(acc[i][j], ahi[i], blo[j]);
                MMA_BF16(acc[i][j], alo[i], bhi[j]);
            }
    }

    const float scale = 0.125f;
    size_t base = (size_t)bh * T_ * S_;
    int g  = lane >> 2;
    int tg = lane & 3;
    #pragma unroll
    for (int i = 0; i < 4; i++) {
        int row = t0 + warp_m * 64 + i * 16 + g;
        #pragma unroll
        for (int j = 0; j < 4; j++) {
            int colb = s0 + warp_n * 32 + j * 8 + 2 * tg;
            *(float2*)&P[base + (size_t)row * S_ + colb] =
                make_float2(acc[i][j][0] * scale, acc[i][j][1] * scale);
            *(float2*)&P[base + (size_t)(row + 8) * S_ + colb] =
                make_float2(acc[i][j][2] * scale, acc[i][j][3] * scale);
        }
    }
}

// ---------------------------------------------------------------------------
// softmax + head-mean attn_w; emits Ph/Pl bf16 split
// ---------------------------------------------------------------------------
__global__ __launch_bounds__(256)
void softmax_attnw(const float* __restrict__ P,
                   __nv_bfloat16* __restrict__ Ph, __nv_bfloat16* __restrict__ Pl,
                   float* __restrict__ Wout, int do_w) {
    int bx = blockIdx.x;
    int b = bx >> 11;
    int t = bx & (T_ - 1);
    int tid = threadIdx.x;
    __shared__ float red[8];

    float wacc[8];
    #pragma unroll
    for (int i = 0; i < 8; i++) wacc[i] = 0.f;

    for (int h = 0; h < H_; h++) {
        size_t rowoff = ((size_t)(b * H_ + h) * T_ + t) * S_;
        const float* p = P + rowoff;
        float v[8];
        float mx = -1e30f;
        #pragma unroll
        for (int i = 0; i < 8; i++) {
            v[i] = p[tid + i * 256];
            mx = fmaxf(mx, v[i]);
        }
        #pragma unroll
        for (int o = 16; o; o >>= 1) mx = fmaxf(mx, __shfl_xor_sync(~0u, mx, o));
        if ((tid & 31) == 0) red[tid >> 5] = mx;
        __syncthreads();
        mx = red[0];
        #pragma unroll
        for (int i = 1; i < 8; i++) mx = fmaxf(mx, red[i]);
        __syncthreads();

        float sum = 0.f;
        #pragma unroll
        for (int i = 0; i < 8; i++) {
            v[i] = __expf(v[i] - mx);
            sum += v[i];
        }
        #pragma unroll
        for (int o = 16; o; o >>= 1) sum += __shfl_xor_sync(~0u, sum, o);
        if ((tid & 31) == 0) red[tid >> 5] = sum;
        __syncthreads();
        sum = 0.f;
        #pragma unroll
        for (int i = 0; i < 8; i++) sum += red[i];
        float inv = 1.0f / sum;
        #pragma unroll
        for (int i = 0; i < 8; i++) {
            float pr = v[i] * inv;
            __nv_bfloat16 hh = __float2bfloat16_rn(pr);
            Ph[rowoff + tid + i * 256] = hh;
            Pl[rowoff + tid + i * 256] = __float2bfloat16_rn(pr - __bfloat162float(hh));
            wacc[i] += pr;
        }
        __syncthreads();
    }

    if (do_w) {
        float* w = Wout + ((size_t)b * T_ + t) * S_;
        #pragma unroll
        for (int i = 0; i < 8; i++) w[tid + i * 256] = wacc[i] * (1.0f / H_);
    }
}

// ---------------------------------------------------------------------------
// PV: O = P @ V, 3-term (Ph.Vh + Ph.Vl + Pl.Vh).  64x64 tile, chunk 64,
// cp.async double-buffered.
// ---------------------------------------------------------------------------
#define MPV    (64 * SKS * 2)        // 9216 per matrix
#define PVBUF  (4 * MPV)             // 36864 per stage
#define SMEM_PV (2 * PVBUF)          // 73728

__device__ __forceinline__ void pv_issue(
    const __nv_bfloat16* Ph, const __nv_bfloat16* Pl,
    const __nv_bfloat16* Vh, const __nv_bfloat16* Vl,
    uint32_t smb, int buf, int k0, int bh, int t0, int tid)
{
    // 4 matrices (64 rows x 64 cols) = 2048 x 16B segments, 8 per thread
    #pragma unroll
    for (int i = 0; i < 8; i++) {
        int u = tid + 256 * i;        // 0..2047
        int mat = u >> 9;             // 0 Ph, 1 Pl, 2 Vh, 3 Vl
        int rem = u & 511;
        int row = rem >> 3;           // 0..63
        int seg = rem & 7;            // 0..7 (64 cols)
        uint32_t dst = smb + (uint32_t)buf * PVBUF + (uint32_t)mat * MPV +
                       (uint32_t)(row * SKS + seg * 8) * 2;
        const __nv_bfloat16* src;
        if (mat < 2)
            src = (mat == 0 ? Ph : Pl) + ((size_t)bh * T_ + t0 + row) * S_ + k0 + seg * 8;
        else
            src = (mat == 2 ? Vh : Vl) + ((size_t)bh * T_ + k0 + row) * HD_ + seg * 8;
        CP16(dst, src);
    }
}

__global__ __launch_bounds__(256)
void pv_mma(const __nv_bfloat16* __restrict__ Ph, const __nv_bfloat16* __restrict__ Pl,
            const __nv_bfloat16* __restrict__ Vh, const __nv_bfloat16* __restrict__ Vl,
            float* __restrict__ O)
{
    extern __shared__ char smn[];
    uint32_t smb = smem_u32(smn);

    int bh = blockIdx.y;
    int b = bh >> 4, h = bh & 15;
    int t0 = blockIdx.x * 64;
    int tid = threadIdx.x;
    int wid = tid >> 5;
    int lane = tid & 31;
    int warp_m = wid >> 1;        // 0..3 (16 t rows)
    int warp_n = wid & 1;         // 0..1 (32 d cols)

    float acc[4][4];
    #pragma unroll
    for (int j = 0; j < 4; j++)
        #pragma unroll
        for (int q = 0; q < 4; q++) acc[j][q] = 0.f;

    int a_row = warp_m * 16 + (lane & 15);
    int a_colk = (lane >> 4) * 8;
    int sub = lane >> 3;
    int tr_row = (sub & 1) * 8 + (lane & 7);
    int tr_col = (sub >> 1) * 8;

    pv_issue(Ph, Pl, Vh, Vl, smb, 0, 0, bh, t0, tid);
    CP_COMMIT();

    for (int c = 0; c < S_ / 64; c++) {
        if (c + 1 < S_ / 64) {
            pv_issue(Ph, Pl, Vh, Vl, smb, (c + 1) & 1, (c + 1) * 64, bh, t0, tid);
            CP_COMMIT();
            CP_WAIT1();
        } else {
            CP_WAIT0();
        }
        __syncthreads();

        int buf = c & 1;
        uint32_t uPh = smb + (uint32_t)buf * PVBUF;
        uint32_t uPl = uPh + MPV;
        uint32_t uVh = uPh + 2 * MPV;
        uint32_t uVl = uPh + 3 * MPV;

        #pragma unroll
        for (int kk = 0; kk < 4; kk++) {
            uint32_t aph[4], apl[4];
            {
                uint32_t off = (uint32_t)((a_row * SKS) + kk * 16 + a_colk) * 2;
                LDMATRIX_X4(aph, uPh + off);
                LDMATRIX_X4(apl, uPl + off);
            }
            uint32_t bhv[4][2], blv[4][2];
            #pragma unroll
            for (int j2 = 0; j2 < 2; j2++) {
                uint32_t off = (uint32_t)(((kk * 16 + tr_row) * SKS) +
                                          warp_n * 32 + j2 * 16 + tr_col) * 2;
                uint32_t t[4];
                LDMATRIX_X4_T(t, uVh + off);
                bhv[j2*2][0] = t[0]; bhv[j2*2][1] = t[1];
                bhv[j2*2+1][0] = t[2]; bhv[j2*2+1][1] = t[3];
                LDMATRIX_X4_T(t, uVl + off);
                blv[j2*2][0] = t[0]; blv[j2*2][1] = t[1];
                blv[j2*2+1][0] = t[2]; blv[j2*2+1][1] = t[3];
            }
            #pragma unroll
            for (int j = 0; j < 4; j++) {
                MMA_BF16(acc[j], aph, bhv[j]);
                MMA_BF16(acc[j], aph, blv[j]);
                MMA_BF16(acc[j], apl, bhv[j]);
            }
        }
        __syncthreads();
    }

    int g  = lane >> 2;
    int tg = lane & 3;
    #pragma unroll
    for (int j = 0; j < 4; j++) {
        int trow = t0 + warp_m * 16 + g;
        int col = h * HD_ + warp_n * 32 + j * 8 + 2 * tg;
        size_t o0 = ((size_t)trow * B_ + b) * E_ + col;
        size_t o1 = ((size_t)(trow + 8) * B_ + b) * E_ + col;
        *(float2*)&O[o0] = make_float2(acc[j][0], acc[j][1]);
        *(float2*)&O[o1] = make_float2(acc[j][2], acc[j][3]);
    }
}

// ---------------------------------------------------------------------------
// Host launcher
// ---------------------------------------------------------------------------
extern "C" void kernel_launch(void* const* d_in, const int* in_sizes, int n_in,
                              void* d_out, int out_size) {
    const float* query = (const float*)d_in[0];
    const float* key   = (const float*)d_in[1];
    const float* value = (const float*)d_in[2];
    const float* q_w  = (const float*)d_in[3];
    const float* q_b  = (const float*)d_in[4];
    const float* q_la = (const float*)d_in[5];
    const float* q_lb = (const float*)d_in[6];
    const float* k_w  = (const float*)d_in[7];
    const float* k_b  = (const float*)d_in[8];
    const float* k_la = (const float*)d_in[9];
    const float* k_lb = (const float*)d_in[10];
    const float* v_w  = (const float*)d_in[11];
    const float* v_b  = (const float*)d_in[12];
    const float* v_la = (const float*)d_in[13];
    const float* v_lb = (const float*)d_in[14];
    const float* o_w  = (const float*)d_in[15];
    const float* o_b  = (const float*)d_in[16];
    const float* o_la = (const float*)d_in[17];
    const float* o_lb = (const float*)d_in[18];

    float *O, *P;
    __nv_bfloat16 *Ph, *Pl, *Qh, *Ql, *Kh, *Kl, *Vh, *Vl;
    __nv_bfloat16 *Ah, *Al, *Wh, *Wl, *lbh, *lbl, *Xah, *Xal;
    cudaGetSymbolAddress((void**)&O,  g_O);
    cudaGetSymbolAddress((void**)&P,  g_P);
    cudaGetSymbolAddress((void**)&Ph, g_Ph);
    cudaGetSymbolAddress((void**)&Pl, g_Pl);
    cudaGetSymbolAddress((void**)&Qh, g_Qh);
    cudaGetSymbolAddress((void**)&Ql, g_Ql);
    cudaGetSymbolAddress((void**)&Kh, g_Kh);
    cudaGetSymbolAddress((void**)&Kl, g_Kl);
    cudaGetSymbolAddress((void**)&Vh, g_Vh);
    cudaGetSymbolAddress((void**)&Vl, g_Vl);
    cudaGetSymbolAddress((void**)&Ah, g_Ah);
    cudaGetSymbolAddress((void**)&Al, g_Al);
    cudaGetSymbolAddress((void**)&Wh, g_Wh);
    cudaGetSymbolAddress((void**)&Wl, g_Wl);
    cudaGetSymbolAddress((void**)&lbh, g_lbh);
    cudaGetSymbolAddress((void**)&lbl, g_lbl);
    cudaGetSymbolAddress((void**)&Xah, g_Xah);
    cudaGetSymbolAddress((void**)&Xal, g_Xal);

    float* out1 = (float*)d_out;
    bool write_attnw = ((size_t)out_size >= OUT1_ELEMS + OUT2_ELEMS);
    float* out2 = out1 + OUT1_ELEMS;

    cudaFuncSetAttribute(gemm2, cudaFuncAttributeMaxDynamicSharedMemorySize, SMEM_G2);
    cudaFuncSetAttribute(scores_mma, cudaFuncAttributeMaxDynamicSharedMemorySize, SMEM_SC);
    cudaFuncSetAttribute(pv_mma, cudaFuncAttributeMaxDynamicSharedMemorySize, SMEM_PV);

    dim3 gGemm(E_ / 128, M_ / 128);       // (8, 32)
    int nX4 = M_ * E_ / 4;                // 1M
    int nW4 = E_ * E_ / 4;                // 256K

    // LoRA-A (padded bf16 hi/lo), slot i
    lora_a2<<<M_, 128>>>(query, q_la, Xah + 0 * M_ * 32, Xal + 0 * M_ * 32);
    lora_a2<<<M_, 128>>>(key,   k_la, Xah + 1 * M_ * 32, Xal + 1 * M_ * 32);
    lora_a2<<<M_, 128>>>(value, v_la, Xah + 2 * M_ * 32, Xal + 2 * M_ * 32);

    // Q projection
    split_mat<<<nX4 / 256, 256>>>(query, Ah, Al, nX4);
    split_mat<<<nW4 / 256, 256>>>(q_w, Wh, Wl, nW4);
    split_lb<<<E_ / 256, 256>>>(q_lb, lbh, lbl);
    gemm2<<<gGemm, 256, SMEM_G2>>>(Ah, Al, Wh, Wl, q_b,
                                   Xah + 0 * M_ * 32, Xal + 0 * M_ * 32, lbh, lbl,
                                   nullptr, Qh, Ql);
    // K projection
    split_mat<<<nX4 / 256, 256>>>(key, Ah, Al, nX4);
    split_mat<<<nW4 / 256, 256>>>(k_w, Wh, Wl, nW4);
    split_lb<<<E_ / 256, 256>>>(k_lb, lbh, lbl);
    gemm2<<<gGemm, 256, SMEM_G2>>>(Ah, Al, Wh, Wl, k_b,
                                   Xah + 1 * M_ * 32, Xal + 1 * M_ * 32, lbh, lbl,
                                   nullptr, Kh, Kl);
    // V projection
    split_mat<<<nX4 / 256, 256>>>(value, Ah, Al, nX4);
    split_mat<<<nW4 / 256, 256>>>(v_w, Wh, Wl, nW4);
    split_lb<<<E_ / 256, 256>>>(v_lb, lbh, lbl);
    gemm2<<<gGemm, 256, SMEM_G2>>>(Ah, Al, Wh, Wl, v_b,
                                   Xah + 2 * M_ * 32, Xal + 2 * M_ * 32, lbh, lbl,
                                   nullptr, Vh, Vl);

    // scores
    dim3 gScores(S_ / 128, T_ / 128, BH_);
    scores_mma<<<gScores, 256, SMEM_SC>>>(Qh, Ql, Kh, Kl, P);

    // softmax + attn_w, emit bf16 split probs
    softmax_attnw<<<B_ * T_, 256>>>(P, Ph, Pl, out2, write_attnw ? 1 : 0);

    // P @ V
    dim3 gPV(T_ / 64, BH_);
    pv_mma<<<gPV, 256, SMEM_PV>>>(Ph, Pl, Vh, Vl, O);

    // output projection
    lora_a2<<<M_, 128>>>(O, o_la, Xah + 3 * M_ * 32, Xal + 3 * M_ * 32);
    split_mat<<<nX4 / 256, 256>>>(O, Ah, Al, nX4);
    split_mat<<<nW4 / 256, 256>>>(o_w, Wh, Wl, nW4);
    split_lb<<<E_ / 256, 256>>>(o_lb, lbh, lbl);
    gemm2<<<gGemm, 256, SMEM_G2>>>(Ah, Al, Wh, Wl, o_b,
                                   Xah + 3 * M_ * 32, Xal + 3 * M_ * 32, lbh, lbl,
                                   out1, nullptr, nullptr);
}

// round 10
// speedup vs baseline: 1.7864x; 1.0409x over previous
#include <cuda_runtime.h>
#include <cuda_bf16.h>
#include <cstdint>
#include <math.h>

// Problem constants
#define T_  2048
#define B_  2
#define S_  2048
#define E_  1024
#define H_  16
#define HD_ 64
#define R_  16
#define M_  (T_ * B_)
#define BH_ (B_ * H_)
#define SCALING 1.0f
#define OUT1_ELEMS ((size_t)T_ * B_ * E_)
#define OUT2_ELEMS ((size_t)B_ * T_ * S_)
#define ME_ ((size_t)M_ * E_)
#define EE_ ((size_t)E_ * E_)

// ---------------------------------------------------------------------------
// Static device scratch
// ---------------------------------------------------------------------------
__device__ float g_O[M_ * E_];                         // attention out (fp32)
__device__ float g_P[(size_t)BH_ * T_ * S_];           // fp32 logits (512MB)
__device__ __nv_bfloat16 g_Ph[(size_t)BH_ * T_ * S_];  // probs hi
__device__ __nv_bfloat16 g_Pl[(size_t)BH_ * T_ * S_];  // probs lo
__device__ __nv_bfloat16 g_Qh[M_ * E_], g_Ql[M_ * E_]; // head-major [bh][t][64]
__device__ __nv_bfloat16 g_Kh[M_ * E_], g_Kl[M_ * E_];
__device__ __nv_bfloat16 g_Vh[M_ * E_], g_Vl[M_ * E_];
__device__ __nv_bfloat16 g_Ah[3 * ME_], g_Al[3 * ME_]; // pre-split A (3 slots)
__device__ __nv_bfloat16 g_Wh[3 * EE_], g_Wl[3 * EE_]; // pre-split W (3 slots)
__device__ __nv_bfloat16 g_lbh[3 * E_ * 32], g_lbl[3 * E_ * 32]; // padded LoRA-B
__device__ __nv_bfloat16 g_Xah[4 * M_ * 32], g_Xal[4 * M_ * 32]; // padded LoRA-A

// ---------------------------------------------------------------------------
// PTX helpers
// ---------------------------------------------------------------------------
__device__ __forceinline__ uint32_t smem_u32(const void* p) {
    uint32_t a;
    asm("{ .reg .u64 t; cvta.to.shared.u64 t, %1; cvt.u32.u64 %0, t; }" : "=r"(a) : "l"(p));
    return a;
}
#define LDMATRIX_X4(r, addr) \
    asm volatile("ldmatrix.sync.aligned.m8n8.x4.shared.b16 {%0,%1,%2,%3}, [%4];" \
        : "=r"((r)[0]), "=r"((r)[1]), "=r"((r)[2]), "=r"((r)[3]) : "r"(addr))
#define LDMATRIX_X4_T(r, addr) \
    asm volatile("ldmatrix.sync.aligned.m8n8.x4.trans.shared.b16 {%0,%1,%2,%3}, [%4];" \
        : "=r"((r)[0]), "=r"((r)[1]), "=r"((r)[2]), "=r"((r)[3]) : "r"(addr))
#define MMA_BF16(d, a, b) \
    asm volatile("mma.sync.aligned.m16n8k16.row.col.f32.bf16.bf16.f32 " \
        "{%0,%1,%2,%3}, {%4,%5,%6,%7}, {%8,%9}, {%0,%1,%2,%3};" \
        : "+f"((d)[0]), "+f"((d)[1]), "+f"((d)[2]), "+f"((d)[3]) \
        : "r"((a)[0]), "r"((a)[1]), "r"((a)[2]), "r"((a)[3]), \
          "r"((b)[0]), "r"((b)[1]))
#define CP16(dst, src) \
    asm volatile("cp.async.cg.shared.global [%0], [%1], 16;" :: "r"(dst), "l"(src))
#define CP_COMMIT() asm volatile("cp.async.commit_group;")
#define CP_WAIT0()  asm volatile("cp.async.wait_group 0;" ::: "memory")
#define CP_WAIT1()  asm volatile("cp.async.wait_group 1;" ::: "memory")

__device__ __forceinline__ void split_pair(float f0, float f1,
                                           __nv_bfloat162* hi, __nv_bfloat162* lo) {
    __nv_bfloat16 h0 = __float2bfloat16_rn(f0);
    __nv_bfloat16 h1 = __float2bfloat16_rn(f1);
    __nv_bfloat16 l0 = __float2bfloat16_rn(f0 - __bfloat162float(h0));
    __nv_bfloat16 l1 = __float2bfloat16_rn(f1 - __bfloat162float(h1));
    *hi = __nv_bfloat162(h0, h1);
    *lo = __nv_bfloat162(l0, l1);
}

// ---------------------------------------------------------------------------
// Split kernels
// ---------------------------------------------------------------------------
__global__ void split_mat(const float* __restrict__ X,
                          __nv_bfloat16* __restrict__ Xh,
                          __nv_bfloat16* __restrict__ Xl, int n4) {
    int i = blockIdx.x * blockDim.x + threadIdx.x;
    if (i >= n4) return;
    float4 v = ((const float4*)X)[i];
    __nv_bfloat162 h0, l0, h1, l1;
    split_pair(v.x, v.y, &h0, &l0);
    split_pair(v.z, v.w, &h1, &l1);
    ((__nv_bfloat162*)Xh)[2 * i]     = h0;
    ((__nv_bfloat162*)Xh)[2 * i + 1] = h1;
    ((__nv_bfloat162*)Xl)[2 * i]     = l0;
    ((__nv_bfloat162*)Xl)[2 * i + 1] = l1;
}

__global__ void split_lb(const float* __restrict__ lb,
                         __nv_bfloat16* __restrict__ lbh,
                         __nv_bfloat16* __restrict__ lbl) {
    int r = blockIdx.x * blockDim.x + threadIdx.x;
    if (r >= E_) return;
    #pragma unroll
    for (int j = 0; j < 16; j += 2) {
        __nv_bfloat162 h, l;
        split_pair(lb[r * R_ + j], lb[r * R_ + j + 1], &h, &l);
        *(__nv_bfloat162*)&lbh[r * 32 + j] = h;
        *(__nv_bfloat162*)&lbl[r * 32 + j] = l;
    }
    __nv_bfloat162 z = __nv_bfloat162(__float2bfloat16_rn(0.f), __float2bfloat16_rn(0.f));
    #pragma unroll
    for (int j = 16; j < 32; j += 2) {
        *(__nv_bfloat162*)&lbh[r * 32 + j] = z;
        *(__nv_bfloat162*)&lbl[r * 32 + j] = z;
    }
}

// ---------------------------------------------------------------------------
// LoRA-A
// ---------------------------------------------------------------------------
__global__ void lora_a2(const float* __restrict__ X, const float* __restrict__ la,
                        __nv_bfloat16* __restrict__ Xah, __nv_bfloat16* __restrict__ Xal) {
    int m = blockIdx.x;
    int t = threadIdx.x;          // 128
    int r  = t & 15;
    int eo = t >> 4;
    const float* x   = X  + (size_t)m * E_;
    const float* lar = la + (size_t)r * E_;
    float acc = 0.f;
    #pragma unroll 8
    for (int e = eo; e < E_; e += 8) acc += x[e] * lar[e];
    __shared__ float sm[16][8];
    sm[r][eo] = acc;
    __syncthreads();
    if (t < 16) {
        float s = 0.f;
        #pragma unroll
        for (int i = 0; i < 8; i++) s += sm[t][i];
        s *= SCALING;
        __nv_bfloat16 h = __float2bfloat16_rn(s);
        __nv_bfloat16 l = __float2bfloat16_rn(s - __bfloat162float(h));
        Xah[(size_t)m * 32 + t] = h;
        Xal[(size_t)m * 32 + t] = l;
    } else if (t < 32) {
        Xah[(size_t)m * 32 + t] = __float2bfloat16_rn(0.f);
        Xal[(size_t)m * 32 + t] = __float2bfloat16_rn(0.f);
    }
}

// ---------------------------------------------------------------------------
// GEMM: 64x128 tile, BK=32, 33 chunks, 2 CTAs/SM, z-fused projections.
// ---------------------------------------------------------------------------
#define SK2   40                    // smem row stride (bf16): 80B
#define A_MB  (64 * SK2 * 2)        // 5120 B
#define W_MB  (128 * SK2 * 2)       // 10240 B
#define STG_B (2 * A_MB + 2 * W_MB) // 30720 per stage
#define NCH   33
#define SMEM_G2 (2 * STG_B + 512)   // 61952

struct G2One {
    const __nv_bfloat16 *Ah, *Al, *Wh, *Wl;
    const float* bias;
    const __nv_bfloat16 *Xah, *Xal, *lbh, *lbl;
    float* C;
    __nv_bfloat16 *Chi, *Clo;
};
struct G2Args { G2One a[3]; };

__device__ __forceinline__ void g2_issue(
    const G2One& g, uint32_t smb, int buf, int chunk, int m0, int n0, int tid)
{
    // A: 2 mats x 64 rows x 4 segs = 512 ; W: 2 mats x 128 rows x 4 segs = 1024
    #pragma unroll
    for (int i = 0; i < 6; i++) {
        int u = tid + 256 * i;        // 0..1535
        const __nv_bfloat16* src;
        uint32_t dst;
        if (u < 512) {
            int mat = u >> 8;         // 0 Ah, 1 Al
            int rem = u & 255;
            int row = rem >> 2;       // 0..63
            int seg = rem & 3;
            dst = smb + (uint32_t)buf * STG_B + (uint32_t)mat * A_MB +
                  (uint32_t)(row * SK2 + seg * 8) * 2;
            if (chunk < 32)
                src = (mat == 0 ? g.Ah : g.Al) + (size_t)(m0 + row) * E_ + chunk * 32 + seg * 8;
            else
                src = (mat == 0 ? g.Xah : g.Xal) + (size_t)(m0 + row) * 32 + seg * 8;
        } else {
            int v = u - 512;
            int mat = v >> 9;         // 0 Wh, 1 Wl
            int rem = v & 511;
            int row = rem >> 2;       // 0..127
            int seg = rem & 3;
            dst = smb + (uint32_t)buf * STG_B + 2 * A_MB + (uint32_t)mat * W_MB +
                  (uint32_t)(row * SK2 + seg * 8) * 2;
            if (chunk < 32)
                src = (mat == 0 ? g.Wh : g.Wl) + (size_t)(n0 + row) * E_ + chunk * 32 + seg * 8;
            else
                src = (mat == 0 ? g.lbh : g.lbl) + (size_t)(n0 + row) * 32 + seg * 8;
        }
        CP16(dst, src);
    }
}

__global__ __launch_bounds__(256, 2)
void gemm2(G2Args args)
{
    extern __shared__ char sm[];
    uint32_t smb = smem_u32(sm);
    float* biasS = (float*)(sm + 2 * STG_B);

    G2One g = args.a[blockIdx.z];

    int tid = threadIdx.x;
    int wid = tid >> 5;
    int lane = tid & 31;
    int warp_m = wid >> 2;          // 0..1  (32 rows each)
    int warp_n = wid & 3;           // 0..3  (32 cols each)
    int m0 = blockIdx.y * 64;
    int n0 = blockIdx.x * 128;

    if (tid < 128) biasS[tid] = g.bias[n0 + tid];

    float acc[2][4][4];
    #pragma unroll
    for (int i = 0; i < 2; i++)
        #pragma unroll
        for (int j = 0; j < 4; j++)
            #pragma unroll
            for (int q = 0; q < 4; q++) acc[i][j][q] = 0.f;

    g2_issue(g, smb, 0, 0, m0, n0, tid);
    CP_COMMIT();

    int a_row = warp_m * 32 + (lane & 15);
    int a_colk = (lane >> 4) * 8;
    int b_row = warp_n * 32 + ((lane >> 4) << 3) + (lane & 7);
    int b_colk = ((lane >> 3) & 1) * 8;

    for (int c = 0; c < NCH; c++) {
        if (c + 1 < NCH) {
            g2_issue(g, smb, (c + 1) & 1, c + 1, m0, n0, tid);
            CP_COMMIT();
            CP_WAIT1();
        } else {
            CP_WAIT0();
        }
        __syncthreads();

        int buf = c & 1;
        uint32_t sAh = smb + (uint32_t)buf * STG_B;
        uint32_t sAl = sAh + A_MB;
        uint32_t sWh = sAh + 2 * A_MB;
        uint32_t sWl = sWh + W_MB;

        #pragma unroll
        for (int kk = 0; kk < 2; kk++) {
            int k0 = kk * 16;
            uint32_t ahi[2][4], alo[2][4];
            #pragma unroll
            for (int i = 0; i < 2; i++) {
                uint32_t off = (uint32_t)(((a_row + i * 16) * SK2) + k0 + a_colk) * 2;
                LDMATRIX_X4(ahi[i], sAh + off);
                LDMATRIX_X4(alo[i], sAl + off);
            }
            uint32_t bhi[4][2], blo[4][2];
            #pragma unroll
            for (int jp = 0; jp < 2; jp++) {
                uint32_t off = (uint32_t)(((b_row + jp * 16) * SK2) + k0 + b_colk) * 2;
                uint32_t t[4];
                LDMATRIX_X4(t, sWh + off);
                bhi[jp*2][0] = t[0]; bhi[jp*2][1] = t[1];
                bhi[jp*2+1][0] = t[2]; bhi[jp*2+1][1] = t[3];
                LDMATRIX_X4(t, sWl + off);
                blo[jp*2][0] = t[0]; blo[jp*2][1] = t[1];
                blo[jp*2+1][0] = t[2]; blo[jp*2+1][1] = t[3];
            }
            #pragma unroll
            for (int i = 0; i < 2; i++)
                #pragma unroll
                for (int j = 0; j < 4; j++) {
                    MMA_BF16(acc[i][j], ahi[i], bhi[j]);
                    MMA_BF16(acc[i][j], ahi[i], blo[j]);
                    MMA_BF16(acc[i][j], alo[i], bhi[j]);
                }
        }
        __syncthreads();
    }

    // epilogue
    int gg = lane >> 2;
    int tg = lane & 3;
    #pragma unroll
    for (int i = 0; i < 2; i++) {
        int row = m0 + warp_m * 32 + i * 16 + gg;
        #pragma unroll
        for (int j = 0; j < 4; j++) {
            int colb = warp_n * 32 + j * 8 + 2 * tg;
            float b0 = biasS[colb], b1 = biasS[colb + 1];
            float v0 = acc[i][j][0] + b0, v1 = acc[i][j][1] + b1;
            float v2 = acc[i][j][2] + b0, v3 = acc[i][j][3] + b1;
            if (g.Chi) {
                // head-major: m = t*B+b ; n = h*64+d -> [(b*H+h)*T + t]*64 + d
                int n = n0 + colb;
                int h = n >> 6, d = n & 63;
                int m0r = row, m1r = row + 8;
                size_t o0 = ((size_t)((m0r & 1) * H_ + h) * T_ + (m0r >> 1)) * HD_ + d;
                size_t o1 = ((size_t)((m1r & 1) * H_ + h) * T_ + (m1r >> 1)) * HD_ + d;
                __nv_bfloat162 hh, ll;
                split_pair(v0, v1, &hh, &ll);
                *(__nv_bfloat162*)&g.Chi[o0] = hh;
                *(__nv_bfloat162*)&g.Clo[o0] = ll;
                split_pair(v2, v3, &hh, &ll);
                *(__nv_bfloat162*)&g.Chi[o1] = hh;
                *(__nv_bfloat162*)&g.Clo[o1] = ll;
            } else {
                size_t o0 = (size_t)row * E_ + n0 + colb;
                size_t o1 = (size_t)(row + 8) * E_ + n0 + colb;
                *(float2*)&g.C[o0] = make_float2(v0, v1);
                *(float2*)&g.C[o1] = make_float2(v2, v3);
            }
        }
    }
}

// ---------------------------------------------------------------------------
// scores: 128x128 tile, head-major bf16 in. (unchanged from R9)
// ---------------------------------------------------------------------------
#define SKS   72
#define MSC   (128 * SKS * 2)
#define SMEM_SC (4 * MSC)           // 73728

__global__ __launch_bounds__(256)
void scores_mma(const __nv_bfloat16* __restrict__ Qh, const __nv_bfloat16* __restrict__ Ql,
                const __nv_bfloat16* __restrict__ Kh, const __nv_bfloat16* __restrict__ Kl,
                float* __restrict__ P)
{
    extern __shared__ char smn[];
    uint32_t smb = smem_u32(smn);

    int bh = blockIdx.z;
    int t0 = blockIdx.y * 128;
    int s0 = blockIdx.x * 128;
    int tid = threadIdx.x;
    int wid = tid >> 5;
    int lane = tid & 31;
    int warp_m = wid >> 2;
    int warp_n = wid & 3;

    #pragma unroll
    for (int i = 0; i < 16; i++) {
        int u = tid + 256 * i;
        int mat = u >> 10;
        int rem = u & 1023;
        int row = rem >> 3;
        int seg = rem & 7;
        uint32_t dst = smb + (uint32_t)mat * MSC + (uint32_t)(row * SKS + seg * 8) * 2;
        const __nv_bfloat16* base = (mat == 0 ? Qh : mat == 1 ? Ql : mat == 2 ? Kh : Kl);
        int r0 = (mat < 2) ? t0 : s0;
        CP16(dst, base + ((size_t)bh * T_ + r0 + row) * HD_ + seg * 8);
    }
    CP_COMMIT();
    CP_WAIT0();
    __syncthreads();

    float acc[4][4][4];
    #pragma unroll
    for (int i = 0; i < 4; i++)
        #pragma unroll
        for (int j = 0; j < 4; j++)
            #pragma unroll
            for (int q = 0; q < 4; q++) acc[i][j][q] = 0.f;

    int a_row = warp_m * 64 + (lane & 15);
    int a_colk = (lane >> 4) * 8;
    int b_row = warp_n * 32 + ((lane >> 4) << 3) + (lane & 7);
    int b_colk = ((lane >> 3) & 1) * 8;
    uint32_t uQh = smb, uQl = smb + MSC, uKh = smb + 2 * MSC, uKl = smb + 3 * MSC;

    #pragma unroll
    for (int kk = 0; kk < 4; kk++) {
        int k0 = kk * 16;
        uint32_t ahi[4][4], alo[4][4];
        #pragma unroll
        for (int i = 0; i < 4; i++) {
            uint32_t off = (uint32_t)(((a_row + i * 16) * SKS) + k0 + a_colk) * 2;
            LDMATRIX_X4(ahi[i], uQh + off);
            LDMATRIX_X4(alo[i], uQl + off);
        }
        uint32_t bhi[4][2], blo[4][2];
        #pragma unroll
        for (int jp = 0; jp < 2; jp++) {
            uint32_t off = (uint32_t)(((b_row + jp * 16) * SKS) + k0 + b_colk) * 2;
            uint32_t t[4];
            LDMATRIX_X4(t, uKh + off);
            bhi[jp*2][0] = t[0]; bhi[jp*2][1] = t[1];
            bhi[jp*2+1][0] = t[2]; bhi[jp*2+1][1] = t[3];
            LDMATRIX_X4(t, uKl + off);
            blo[jp*2][0] = t[0]; blo[jp*2][1] = t[1];
            blo[jp*2+1][0] = t[2]; blo[jp*2+1][1] = t[3];
        }
        #pragma unroll
        for (int i = 0; i < 4; i++)
            #pragma unroll
            for (int j = 0; j < 4; j++) {
                MMA_BF16(acc[i][j], ahi[i], bhi[j]);
                MMA_BF16(acc[i][j], ahi[i], blo[j]);
                MMA_BF16(acc[i][j], alo[i], bhi[j]);
            }
    }

    const float scale = 0.125f;
    size_t base = (size_t)bh * T_ * S_;
    int g  = lane >> 2;
    int tg = lane & 3;
    #pragma unroll
    for (int i = 0; i < 4; i++) {
        int row = t0 + warp_m * 64 + i * 16 + g;
        #pragma unroll
        for (int j = 0; j < 4; j++) {
            int colb = s0 + warp_n * 32 + j * 8 + 2 * tg;
            *(float2*)&P[base + (size_t)row * S_ + colb] =
                make_float2(acc[i][j][0] * scale, acc[i][j][1] * scale);
            *(float2*)&P[base + (size_t)(row + 8) * S_ + colb] =
                make_float2(acc[i][j][2] * scale, acc[i][j][3] * scale);
        }
    }
}

// ---------------------------------------------------------------------------
// softmax + head-mean attn_w; emits Ph/Pl bf16 split (unchanged)
// ---------------------------------------------------------------------------
__global__ __launch_bounds__(256)
void softmax_attnw(const float* __restrict__ P,
                   __nv_bfloat16* __restrict__ Ph, __nv_bfloat16* __restrict__ Pl,
                   float* __restrict__ Wout, int do_w) {
    int bx = blockIdx.x;
    int b = bx >> 11;
    int t = bx & (T_ - 1);
    int tid = threadIdx.x;
    __shared__ float red[8];

    float wacc[8];
    #pragma unroll
    for (int i = 0; i < 8; i++) wacc[i] = 0.f;

    for (int h = 0; h < H_; h++) {
        size_t rowoff = ((size_t)(b * H_ + h) * T_ + t) * S_;
        const float* p = P + rowoff;
        float v[8];
        float mx = -1e30f;
        #pragma unroll
        for (int i = 0; i < 8; i++) {
            v[i] = p[tid + i * 256];
            mx = fmaxf(mx, v[i]);
        }
        #pragma unroll
        for (int o = 16; o; o >>= 1) mx = fmaxf(mx, __shfl_xor_sync(~0u, mx, o));
        if ((tid & 31) == 0) red[tid >> 5] = mx;
        __syncthreads();
        mx = red[0];
        #pragma unroll
        for (int i = 1; i < 8; i++) mx = fmaxf(mx, red[i]);
        __syncthreads();

        float sum = 0.f;
        #pragma unroll
        for (int i = 0; i < 8; i++) {
            v[i] = __expf(v[i] - mx);
            sum += v[i];
        }
        #pragma unroll
        for (int o = 16; o; o >>= 1) sum += __shfl_xor_sync(~0u, sum, o);
        if ((tid & 31) == 0) red[tid >> 5] = sum;
        __syncthreads();
        sum = 0.f;
        #pragma unroll
        for (int i = 0; i < 8; i++) sum += red[i];
        float inv = 1.0f / sum;
        #pragma unroll
        for (int i = 0; i < 8; i++) {
            float pr = v[i] * inv;
            __nv_bfloat16 hh = __float2bfloat16_rn(pr);
            Ph[rowoff + tid + i * 256] = hh;
            Pl[rowoff + tid + i * 256] = __float2bfloat16_rn(pr - __bfloat162float(hh));
            wacc[i] += pr;
        }
        __syncthreads();
    }

    if (do_w) {
        float* w = Wout + ((size_t)b * T_ + t) * S_;
        #pragma unroll
        for (int i = 0; i < 8; i++) w[tid + i * 256] = wacc[i] * (1.0f / H_);
    }
}

// ---------------------------------------------------------------------------
// PV: 64x64 tile, chunk 64, 3-term, cp.async double-buffered (unchanged)
// ---------------------------------------------------------------------------
#define MPV    (64 * SKS * 2)
#define PVBUF  (4 * MPV)
#define SMEM_PV (2 * PVBUF)

__device__ __forceinline__ void pv_issue(
    const __nv_bfloat16* Ph, const __nv_bfloat16* Pl,
    const __nv_bfloat16* Vh, const __nv_bfloat16* Vl,
    uint32_t smb, int buf, int k0, int bh, int t0, int tid)
{
    #pragma unroll
    for (int i = 0; i < 8; i++) {
        int u = tid + 256 * i;
        int mat = u >> 9;
        int rem = u & 511;
        int row = rem >> 3;
        int seg = rem & 7;
        uint32_t dst = smb + (uint32_t)buf * PVBUF + (uint32_t)mat * MPV +
                       (uint32_t)(row * SKS + seg * 8) * 2;
        const __nv_bfloat16* src;
        if (mat < 2)
            src = (mat == 0 ? Ph : Pl) + ((size_t)bh * T_ + t0 + row) * S_ + k0 + seg * 8;
        else
            src = (mat == 2 ? Vh : Vl) + ((size_t)bh * T_ + k0 + row) * HD_ + seg * 8;
        CP16(dst, src);
    }
}

__global__ __launch_bounds__(256)
void pv_mma(const __nv_bfloat16* __restrict__ Ph, const __nv_bfloat16* __restrict__ Pl,
            const __nv_bfloat16* __restrict__ Vh, const __nv_bfloat16* __restrict__ Vl,
            float* __restrict__ O)
{
    extern __shared__ char smn[];
    uint32_t smb = smem_u32(smn);

    int bh = blockIdx.y;
    int b = bh >> 4, h = bh & 15;
    int t0 = blockIdx.x * 64;
    int tid = threadIdx.x;
    int wid = tid >> 5;
    int lane = tid & 31;
    int warp_m = wid >> 1;
    int warp_n = wid & 1;

    float acc[4][4];
    #pragma unroll
    for (int j = 0; j < 4; j++)
        #pragma unroll
        for (int q = 0; q < 4; q++) acc[j][q] = 0.f;

    int a_row = warp_m * 16 + (lane & 15);
    int a_colk = (lane >> 4) * 8;
    int sub = lane >> 3;
    int tr_row = (sub & 1) * 8 + (lane & 7);
    int tr_col = (sub >> 1) * 8;

    pv_issue(Ph, Pl, Vh, Vl, smb, 0, 0, bh, t0, tid);
    CP_COMMIT();

    for (int c = 0; c < S_ / 64; c++) {
        if (c + 1 < S_ / 64) {
            pv_issue(Ph, Pl, Vh, Vl, smb, (c + 1) & 1, (c + 1) * 64, bh, t0, tid);
            CP_COMMIT();
            CP_WAIT1();
        } else {
            CP_WAIT0();
        }
        __syncthreads();

        int buf = c & 1;
        uint32_t uPh = smb + (uint32_t)buf * PVBUF;
        uint32_t uPl = uPh + MPV;
        uint32_t uVh = uPh + 2 * MPV;
        uint32_t uVl = uPh + 3 * MPV;

        #pragma unroll
        for (int kk = 0; kk < 4; kk++) {
            uint32_t aph[4], apl[4];
            {
                uint32_t off = (uint32_t)((a_row * SKS) + kk * 16 + a_colk) * 2;
                LDMATRIX_X4(aph, uPh + off);
                LDMATRIX_X4(apl, uPl + off);
            }
            uint32_t bhv[4][2], blv[4][2];
            #pragma unroll
            for (int j2 = 0; j2 < 2; j2++) {
                uint32_t off = (uint32_t)(((kk * 16 + tr_row) * SKS) +
                                          warp_n * 32 + j2 * 16 + tr_col) * 2;
                uint32_t t[4];
                LDMATRIX_X4_T(t, uVh + off);
                bhv[j2*2][0] = t[0]; bhv[j2*2][1] = t[1];
                bhv[j2*2+1][0] = t[2]; bhv[j2*2+1][1] = t[3];
                LDMATRIX_X4_T(t, uVl + off);
                blv[j2*2][0] = t[0]; blv[j2*2][1] = t[1];
                blv[j2*2+1][0] = t[2]; blv[j2*2+1][1] = t[3];
            }
            #pragma unroll
            for (int j = 0; j < 4; j++) {
                MMA_BF16(acc[j], aph, bhv[j]);
                MMA_BF16(acc[j], aph, blv[j]);
                MMA_BF16(acc[j], apl, bhv[j]);
            }
        }
        __syncthreads();
    }

    int g  = lane >> 2;
    int tg = lane & 3;
    #pragma unroll
    for (int j = 0; j < 4; j++) {
        int trow = t0 + warp_m * 16 + g;
        int col = h * HD_ + warp_n * 32 + j * 8 + 2 * tg;
        size_t o0 = ((size_t)trow * B_ + b) * E_ + col;
        size_t o1 = ((size_t)(trow + 8) * B_ + b) * E_ + col;
        *(float2*)&O[o0] = make_float2(acc[j][0], acc[j][1]);
        *(float2*)&O[o1] = make_float2(acc[j][2], acc[j][3]);
    }
}

// ---------------------------------------------------------------------------
// Host launcher
// ---------------------------------------------------------------------------
extern "C" void kernel_launch(void* const* d_in, const int* in_sizes, int n_in,
                              void* d_out, int out_size) {
    const float* query = (const float*)d_in[0];
    const float* key   = (const float*)d_in[1];
    const float* value = (const float*)d_in[2];
    const float* q_w  = (const float*)d_in[3];
    const float* q_b  = (const float*)d_in[4];
    const float* q_la = (const float*)d_in[5];
    const float* q_lb = (const float*)d_in[6];
    const float* k_w  = (const float*)d_in[7];
    const float* k_b  = (const float*)d_in[8];
    const float* k_la = (const float*)d_in[9];
    const float* k_lb = (const float*)d_in[10];
    const float* v_w  = (const float*)d_in[11];
    const float* v_b  = (const float*)d_in[12];
    const float* v_la = (const float*)d_in[13];
    const float* v_lb = (const float*)d_in[14];
    const float* o_w  = (const float*)d_in[15];
    const float* o_b  = (const float*)d_in[16];
    const float* o_la = (const float*)d_in[17];
    const float* o_lb = (const float*)d_in[18];

    float *O, *P;
    __nv_bfloat16 *Ph, *Pl, *Qh, *Ql, *Kh, *Kl, *Vh, *Vl;
    __nv_bfloat16 *Ah, *Al, *Wh, *Wl, *lbh, *lbl, *Xah, *Xal;
    cudaGetSymbolAddress((void**)&O,  g_O);
    cudaGetSymbolAddress((void**)&P,  g_P);
    cudaGetSymbolAddress((void**)&Ph, g_Ph);
    cudaGetSymbolAddress((void**)&Pl, g_Pl);
    cudaGetSymbolAddress((void**)&Qh, g_Qh);
    cudaGetSymbolAddress((void**)&Ql, g_Ql);
    cudaGetSymbolAddress((void**)&Kh, g_Kh);
    cudaGetSymbolAddress((void**)&Kl, g_Kl);
    cudaGetSymbolAddress((void**)&Vh, g_Vh);
    cudaGetSymbolAddress((void**)&Vl, g_Vl);
    cudaGetSymbolAddress((void**)&Ah, g_Ah);
    cudaGetSymbolAddress((void**)&Al, g_Al);
    cudaGetSymbolAddress((void**)&Wh, g_Wh);
    cudaGetSymbolAddress((void**)&Wl, g_Wl);
    cudaGetSymbolAddress((void**)&lbh, g_lbh);
    cudaGetSymbolAddress((void**)&lbl, g_lbl);
    cudaGetSymbolAddress((void**)&Xah, g_Xah);
    cudaGetSymbolAddress((void**)&Xal, g_Xal);

    float* out1 = (float*)d_out;
    bool write_attnw = ((size_t)out_size >= OUT1_ELEMS + OUT2_ELEMS);
    float* out2 = out1 + OUT1_ELEMS;

    cudaFuncSetAttribute(gemm2, cudaFuncAttributeMaxDynamicSharedMemorySize, SMEM_G2);
    cudaFuncSetAttribute(scores_mma, cudaFuncAttributeMaxDynamicSharedMemorySize, SMEM_SC);
    cudaFuncSetAttribute(pv_mma, cudaFuncAttributeMaxDynamicSharedMemorySize, SMEM_PV);

    int nX4 = (int)(ME_ / 4);
    int nW4 = (int)(EE_ / 4);

    // LoRA-A for q,k,v
    lora_a2<<<M_, 128>>>(query, q_la, Xah + 0 * (size_t)M_ * 32, Xal + 0 * (size_t)M_ * 32);
    lora_a2<<<M_, 128>>>(key,   k_la, Xah + 1 * (size_t)M_ * 32, Xal + 1 * (size_t)M_ * 32);
    lora_a2<<<M_, 128>>>(value, v_la, Xah + 2 * (size_t)M_ * 32, Xal + 2 * (size_t)M_ * 32);

    // All QKV splits up front (separate slots)
    split_mat<<<nX4 / 256, 256>>>(query, Ah + 0 * ME_, Al + 0 * ME_, nX4);
    split_mat<<<nX4 / 256, 256>>>(key,   Ah + 1 * ME_, Al + 1 * ME_, nX4);
    split_mat<<<nX4 / 256, 256>>>(value, Ah + 2 * ME_, Al + 2 * ME_, nX4);
    split_mat<<<nW4 / 256, 256>>>(q_w, Wh + 0 * EE_, Wl + 0 * EE_, nW4);
    split_mat<<<nW4 / 256, 256>>>(k_w, Wh + 1 * EE_, Wl + 1 * EE_, nW4);
    split_mat<<<nW4 / 256, 256>>>(v_w, Wh + 2 * EE_, Wl + 2 * EE_, nW4);
    split_lb<<<E_ / 256, 256>>>(q_lb, lbh + 0 * E_ * 32, lbl + 0 * E_ * 32);
    split_lb<<<E_ / 256, 256>>>(k_lb, lbh + 1 * E_ * 32, lbl + 1 * E_ * 32);
    split_lb<<<E_ / 256, 256>>>(v_lb, lbh + 2 * E_ * 32, lbl + 2 * E_ * 32);

    // Fused QKV projection: grid z = 0,1,2
    {
        G2Args args;
        const float* biases[3] = {q_b, k_b, v_b};
        __nv_bfloat16* chis[3] = {Qh, Kh, Vh};
        __nv_bfloat16* clos[3] = {Ql, Kl, Vl};
        for (int z = 0; z < 3; z++) {
            args.a[z].Ah = Ah + z * ME_;   args.a[z].Al = Al + z * ME_;
            args.a[z].Wh = Wh + z * EE_;   args.a[z].Wl = Wl + z * EE_;
            args.a[z].bias = biases[z];
            args.a[z].Xah = Xah + (size_t)z * M_ * 32;
            args.a[z].Xal = Xal + (size_t)z * M_ * 32;
            args.a[z].lbh = lbh + (size_t)z * E_ * 32;
            args.a[z].lbl = lbl + (size_t)z * E_ * 32;
            args.a[z].C = nullptr;
            args.a[z].Chi = chis[z];
            args.a[z].Clo = clos[z];
        }
        dim3 grid(E_ / 128, M_ / 64, 3);   // (8, 64, 3)
        gemm2<<<grid, 256, SMEM_G2>>>(args);
    }

    // scores
    dim3 gScores(S_ / 128, T_ / 128, BH_);
    scores_mma<<<gScores, 256, SMEM_SC>>>(Qh, Ql, Kh, Kl, P);

    // softmax + attn_w
    softmax_attnw<<<B_ * T_, 256>>>(P, Ph, Pl, out2, write_attnw ? 1 : 0);

    // P @ V
    dim3 gPV(T_ / 64, BH_);
    pv_mma<<<gPV, 256, SMEM_PV>>>(Ph, Pl, Vh, Vl, O);

    // output projection (reuse slot 0 buffers)
    lora_a2<<<M_, 128>>>(O, o_la, Xah + 3 * (size_t)M_ * 32, Xal + 3 * (size_t)M_ * 32);
    split_mat<<<nX4 / 256, 256>>>(O, Ah, Al, nX4);
    split_mat<<<nW4 / 256, 256>>>(o_w, Wh, Wl, nW4);
    split_lb<<<E_ / 256, 256>>>(o_lb, lbh, lbl);
    {
        G2Args args;
        args.a[0].Ah = Ah;  args.a[0].Al = Al;
        args.a[0].Wh = Wh;  args.a[0].Wl = Wl;
        args.a[0].bias = o_b;
        args.a[0].Xah = Xah + 3 * (size_t)M_ * 32;
        args.a[0].Xal = Xal + 3 * (size_t)M_ * 32;
        args.a[0].lbh = lbh; args.a[0].lbl = lbl;
        args.a[0].C = out1;
        args.a[0].Chi = nullptr;
        args.a[0].Clo = nullptr;
        args.a[1] = args.a[0];
        args.a[2] = args.a[0];
        dim3 grid(E_ / 128, M_ / 64, 1);   // (8, 64)
        gemm2<<<grid, 256, SMEM_G2>>>(args);
    }
}